// round 13
// baseline (speedup 1.0000x reference)
#include <cuda_runtime.h>
#include <cuda_bf16.h>
#include <cstdint>

#define DINLINE __device__ __forceinline__

// ---------------- scratch (device globals; no runtime allocation) ----------
__device__ float g_partial[256];
__device__ float g_scales[4096];                          // gamma/127 per token
__device__ float g_alpha_out;
__device__ __align__(128) __nv_bfloat16 g_wqh[16777216];  // W ternary bf16 [N,K]
__device__ __align__(128) __nv_bfloat16 g_xqh[16777216];  // x quant  bf16 [M,K]

// ---------------- PTX helpers (baseline ISA only) ---------------------------
DINLINE uint32_t smem_u32(const void* p) {
    uint32_t a;
    asm("{ .reg .u64 t; cvta.to.shared.u64 t, %1; cvt.u32.u64 %0, t; }"
        : "=r"(a) : "l"(p));
    return a;
}
DINLINE void cp16(uint32_t dst, const void* src) {
    asm volatile("cp.async.cg.shared.global [%0], [%1], 16;" :: "r"(dst), "l"(src));
}
DINLINE void cp_commit() { asm volatile("cp.async.commit_group;" ::: "memory"); }
DINLINE void cp_wait1()  { asm volatile("cp.async.wait_group 1;" ::: "memory"); }

DINLINE void ldsm_x4(uint32_t& r0, uint32_t& r1, uint32_t& r2, uint32_t& r3, uint32_t addr) {
    asm volatile("ldmatrix.sync.aligned.m8n8.x4.shared.b16 {%0,%1,%2,%3}, [%4];"
                 : "=r"(r0), "=r"(r1), "=r"(r2), "=r"(r3) : "r"(addr));
}
DINLINE void mma_bf16(float* c, uint32_t a0, uint32_t a1, uint32_t a2, uint32_t a3,
                      uint32_t b0, uint32_t b1) {
    asm volatile(
        "mma.sync.aligned.m16n8k16.row.col.f32.bf16.bf16.f32 "
        "{%0,%1,%2,%3}, {%4,%5,%6,%7}, {%8,%9}, {%0,%1,%2,%3};"
        : "+f"(c[0]), "+f"(c[1]), "+f"(c[2]), "+f"(c[3])
        : "r"(a0), "r"(a1), "r"(a2), "r"(a3), "r"(b0), "r"(b1));
}
DINLINE int clampi(int v, int lo, int hi) { return v < lo ? lo : (v > hi ? hi : v); }
DINLINE uint32_t pack_bf16(float a, float b) {
    __nv_bfloat162 h;
    h.x = __float2bfloat16(a);
    h.y = __float2bfloat16(b);
    return *reinterpret_cast<uint32_t*>(&h);
}

// ---------------- kernel 1: |W| partial sums ---------------------------------
__global__ void __launch_bounds__(256) k_abs_partial(const float4* __restrict__ w) {
    __shared__ float red[256];
    const int b = blockIdx.x, t = threadIdx.x;
    const float4* p = w + (size_t)b * 16384;
    float s = 0.f;
#pragma unroll 8
    for (int i = 0; i < 64; i++) {
        float4 v = p[t + 256 * i];
        s += fabsf(v.x) + fabsf(v.y) + fabsf(v.z) + fabsf(v.w);
    }
    red[t] = s; __syncthreads();
#pragma unroll
    for (int o = 128; o > 0; o >>= 1) { if (t < o) red[t] += red[t + o]; __syncthreads(); }
    if (t == 0) g_partial[b] = red[0];
}

// ---------------- kernel 2: merged quantization ------------------------------
// Blocks [0,16384): finalize alpha per-block + ternary-quantize W -> bf16.
// Blocks [16384,20480): RMSNorm + int8-grid quantize one x row -> bf16.
// g_scales stores gamma/127 only; GEMM epilogues multiply by g_alpha_out.
__global__ void __launch_bounds__(256) k_quant(const float4* __restrict__ w,
                                               const float* __restrict__ x,
                                               const float* __restrict__ nw) {
    __shared__ float red[256];
    const int t = threadIdx.x;

    if (blockIdx.x < 16384) {
        // ---- W path ----
        red[t] = g_partial[t]; __syncthreads();
#pragma unroll
        for (int o = 128; o > 0; o >>= 1) { if (t < o) red[t] += red[t + o]; __syncthreads(); }
        const float alpha = fmaxf(red[0] * (1.0f / 16777216.0f), 1e-10f);
        if (blockIdx.x == 0 && t == 0) g_alpha_out = alpha;
        const float inv_alpha = 1.0f / alpha;

        const int idx = blockIdx.x * 256 + t;      // float4 index, 4194304 total
        float4 v = w[idx];
        int q0 = clampi(__float2int_rn(v.x * inv_alpha), -1, 1);
        int q1 = clampi(__float2int_rn(v.y * inv_alpha), -1, 1);
        int q2 = clampi(__float2int_rn(v.z * inv_alpha), -1, 1);
        int q3 = clampi(__float2int_rn(v.w * inv_alpha), -1, 1);
        uint2 h;
        h.x = pack_bf16((float)q0, (float)q1);
        h.y = pack_bf16((float)q2, (float)q3);
        reinterpret_cast<uint2*>(g_wqh)[idx] = h;
        return;
    }

    // ---- x path ----
    const int m = blockIdx.x - 16384;
    const float4* xr = reinterpret_cast<const float4*>(x + (size_t)m * 4096);
    const float4* nwr = reinterpret_cast<const float4*>(nw);

    float4 v[4], g[4];
    float ss = 0.f;
#pragma unroll
    for (int i = 0; i < 4; i++) {
        v[i] = xr[t + 256 * i];
        g[i] = nwr[t + 256 * i];
        ss += v[i].x * v[i].x + v[i].y * v[i].y + v[i].z * v[i].z + v[i].w * v[i].w;
    }
    red[t] = ss; __syncthreads();
#pragma unroll
    for (int o = 128; o > 0; o >>= 1) { if (t < o) red[t] += red[t + o]; __syncthreads(); }
    const float rinv = 1.0f / sqrtf(red[0] * (1.0f / 4096.0f) + 1e-6f);
    __syncthreads();

    float mx = 0.f;
#pragma unroll
    for (int i = 0; i < 4; i++) {
        v[i].x *= rinv * g[i].x; v[i].y *= rinv * g[i].y;
        v[i].z *= rinv * g[i].z; v[i].w *= rinv * g[i].w;
        mx = fmaxf(mx, fmaxf(fmaxf(fabsf(v[i].x), fabsf(v[i].y)),
                             fmaxf(fabsf(v[i].z), fabsf(v[i].w))));
    }
    red[t] = mx; __syncthreads();
#pragma unroll
    for (int o = 128; o > 0; o >>= 1) { if (t < o) red[t] = fmaxf(red[t], red[t + o]); __syncthreads(); }
    const float gamma = fmaxf(red[0], 1e-10f);
    if (t == 0) g_scales[m] = gamma * (1.0f / 127.0f);   // alpha applied in epilogue
    const float qs = 127.0f / gamma;
    uint2* dsth = reinterpret_cast<uint2*>(g_xqh) + (size_t)m * 1024;
#pragma unroll
    for (int i = 0; i < 4; i++) {
        int q0 = clampi(__float2int_rn(v[i].x * qs), -128, 127);
        int q1 = clampi(__float2int_rn(v[i].y * qs), -128, 127);
        int q2 = clampi(__float2int_rn(v[i].z * qs), -128, 127);
        int q3 = clampi(__float2int_rn(v[i].w * qs), -128, 127);
        uint2 h;
        h.x = pack_bf16((float)q0, (float)q1);
        h.y = pack_bf16((float)q2, (float)q3);
        dsth[t + 256 * i] = h;
    }
}

// Tile numbering: big-tile id T in [0,512): n0 = (T & 15)*256, m0 = (T >> 4)*128.
// Big kernel: T in [0,444) = exactly 3 clean waves of 148.
// Rem kernel: T in [444,512) as 136 M-split tiles of 64x256 (one partial wave).
static constexpr int BIG_TILES = 444;

static constexpr int LDS_PADH = 144;

// ================= GEMM big: 128x256 tile, 8 warps of 64x64 (R12 body) ======
static constexpr int A_SZ   = 128 * LDS_PADH;        // 18432
static constexpr int B_SZ   = 256 * LDS_PADH;        // 36864
static constexpr int STAGEH = A_SZ + B_SZ;           // 55296
static constexpr int SMEMH  = 4 * STAGEH;            // 221184

__global__ void __launch_bounds__(256, 1) k_gemm_big(float* __restrict__ out) {
    extern __shared__ char smemraw[];
    const uint32_t sbase = smem_u32(smemraw);
    const int t = threadIdx.x;
    const int lane = t & 31, wid = t >> 5;
    const int warpM = wid >> 2;          // 0..1  -> 64-row M slab
    const int warpN = wid & 3;           // 0..3  -> 64-col N slab
    const int T = blockIdx.x;
    const int m0 = (T >> 4) * 128, n0 = (T & 15) * 256;

    const char* gA = reinterpret_cast<const char*>(g_xqh) + (size_t)m0 * 8192;
    const char* gB = reinterpret_cast<const char*>(g_wqh) + (size_t)n0 * 8192;

    const int lr = t >> 1;               // 0..127
    const int lc = (t & 1) * 64;         // 0 or 64
    const char* pA = gA + (size_t)lr * 8192 + lc;
    const char* pB = gB + (size_t)lr * 8192 + lc;
    const uint32_t offA  = (uint32_t)(lr * LDS_PADH + lc);
    const uint32_t offB1 = (uint32_t)(A_SZ + lr * LDS_PADH + lc);
    const uint32_t offB2 = offB1 + 128 * LDS_PADH;

    const int xrow = (lane & 7) + ((lane >> 3) & 1) * 8;
    const int xcol = (lane >> 4) * 16;
    const uint32_t baseA = (uint32_t)((warpM * 64 + xrow) * LDS_PADH + xcol);
    const uint32_t baseB = (uint32_t)(A_SZ + (warpN * 64 + xrow) * LDS_PADH + xcol);

    float acc[4][8][4];
#pragma unroll
    for (int i = 0; i < 4; i++)
#pragma unroll
        for (int j = 0; j < 8; j++)
#pragma unroll
            for (int q = 0; q < 4; q++) acc[i][j][q] = 0.f;

    auto load_stage = [&](int s, int c) {
        const uint32_t dst = sbase + s * STAGEH;
        const char* sA = pA + (size_t)c * 128;
        const char* sB = pB + (size_t)c * 128;
#pragma unroll
        for (int i = 0; i < 4; i++) cp16(dst + offA  + i * 16, sA + i * 16);
#pragma unroll
        for (int i = 0; i < 4; i++) cp16(dst + offB1 + i * 16, sB + i * 16);
#pragma unroll
        for (int i = 0; i < 4; i++) cp16(dst + offB2 + i * 16, sB + (size_t)128 * 8192 + i * 16);
    };

    uint32_t a[2][4][4];
    uint32_t b[2][8][2];

    auto load_frags = [&](int buf, uint32_t st, int kk) {
#pragma unroll
        for (int i = 0; i < 4; i++)
            ldsm_x4(a[buf][i][0], a[buf][i][1], a[buf][i][2], a[buf][i][3],
                    st + baseA + i * (16 * LDS_PADH) + kk * 32);
#pragma unroll
        for (int j2 = 0; j2 < 4; j2++) {
            uint32_t q0, q1, q2, q3;
            ldsm_x4(q0, q1, q2, q3,
                    st + baseB + j2 * (16 * LDS_PADH) + kk * 32);
            b[buf][2 * j2][0] = q0; b[buf][2 * j2 + 1][0] = q1;
            b[buf][2 * j2][1] = q2; b[buf][2 * j2 + 1][1] = q3;
        }
    };

#pragma unroll
    for (int c = 0; c < 3; c++) { load_stage(c, c); cp_commit(); }
    cp_wait1();
    __syncthreads();
    load_frags(0, sbase, 0);

    for (int c = 0; c < 64; c++) {
        cp_wait1();
        __syncthreads();

        const int kn = c + 3;
        if (kn < 64) load_stage(kn & 3, kn);
        cp_commit();

        const uint32_t stC  = sbase + (c & 3) * STAGEH;
        const uint32_t stC1 = sbase + ((c + 1) & 3) * STAGEH;

#pragma unroll
        for (int kk = 0; kk < 4; kk++) {
            const int cur = kk & 1;
            const int nxt = cur ^ 1;
            if (kk < 3)        load_frags(nxt, stC, kk + 1);
            else if (c < 63)   load_frags(nxt, stC1, 0);
#pragma unroll
            for (int i = 0; i < 4; i++)
#pragma unroll
                for (int j = 0; j < 8; j++)
                    mma_bf16(acc[i][j], a[cur][i][0], a[cur][i][1],
                             a[cur][i][2], a[cur][i][3],
                             b[cur][j][0], b[cur][j][1]);
        }
    }

    const float alpha = g_alpha_out;
    const int rq = lane >> 2;
    const int cq = (lane & 3) * 2;
    const int nwcol = n0 + warpN * 64 + cq;
#pragma unroll
    for (int i = 0; i < 4; i++) {
        const int row = m0 + warpM * 64 + i * 16 + rq;
        const float s0 = g_scales[row] * alpha;
        const float s1 = g_scales[row + 8] * alpha;
        float* o0 = out + (size_t)row * 4096 + nwcol;
        float* o1 = o0 + (size_t)8 * 4096;
#pragma unroll
        for (int j = 0; j < 8; j++) {
            float2 v0; v0.x = acc[i][j][0] * s0; v0.y = acc[i][j][1] * s0;
            *reinterpret_cast<float2*>(o0 + j * 8) = v0;
            float2 v1; v1.x = acc[i][j][2] * s1; v1.y = acc[i][j][3] * s1;
            *reinterpret_cast<float2*>(o1 + j * 8) = v1;
        }
    }
}

// ================= GEMM rem: 64x256 tile, 8 warps of 32x64 ==================
// Same per-warp efficiency class as the big body (64-col B slab), half the M.
static constexpr int AR_SZ   = 64 * LDS_PADH;        // 9216
static constexpr int BR_SZ   = 256 * LDS_PADH;       // 36864
static constexpr int STAGER  = AR_SZ + BR_SZ;        // 46080
static constexpr int SMEMR   = 4 * STAGER;           // 184320

__global__ void __launch_bounds__(256, 1) k_gemm_rem(float* __restrict__ out) {
    extern __shared__ char smemraw[];
    const uint32_t sbase = smem_u32(smemraw);
    const int t = threadIdx.x;
    const int lane = t & 31, wid = t >> 5;
    const int warpM = wid >> 2;          // 0..1 -> 32-row M slab
    const int warpN = wid & 3;           // 0..3 -> 64-col N slab
    const int S = blockIdx.x;            // 0..135
    const int T = BIG_TILES + (S >> 1);
    const int m0 = (T >> 4) * 128 + (S & 1) * 64;
    const int n0 = (T & 15) * 256;

    const char* gA = reinterpret_cast<const char*>(g_xqh) + (size_t)m0 * 8192;
    const char* gB = reinterpret_cast<const char*>(g_wqh) + (size_t)n0 * 8192;

    // loader: B as in big kernel (all 256 threads, rows lr and lr+128);
    // A only by threads t<128 (64 rows x 2 half-rows).
    const int lr = t >> 1;               // 0..127
    const int lc = (t & 1) * 64;
    const char* pA = gA + (size_t)lr * 8192 + lc;   // valid only t<128 (lr<64)
    const char* pB = gB + (size_t)lr * 8192 + lc;
    const uint32_t offA  = (uint32_t)(lr * LDS_PADH + lc);
    const uint32_t offB1 = (uint32_t)(AR_SZ + lr * LDS_PADH + lc);
    const uint32_t offB2 = offB1 + 128 * LDS_PADH;
    const bool doA = (t < 128);

    const int xrow = (lane & 7) + ((lane >> 3) & 1) * 8;
    const int xcol = (lane >> 4) * 16;
    const uint32_t baseA = (uint32_t)((warpM * 32 + xrow) * LDS_PADH + xcol);
    const uint32_t baseB = (uint32_t)(AR_SZ + (warpN * 64 + xrow) * LDS_PADH + xcol);

    float acc[2][8][4];
#pragma unroll
    for (int i = 0; i < 2; i++)
#pragma unroll
        for (int j = 0; j < 8; j++)
#pragma unroll
            for (int q = 0; q < 4; q++) acc[i][j][q] = 0.f;

    auto load_stage = [&](int s, int c) {
        const uint32_t dst = sbase + s * STAGER;
        const char* sB = pB + (size_t)c * 128;
        if (doA) {
            const char* sA = pA + (size_t)c * 128;
#pragma unroll
            for (int i = 0; i < 4; i++) cp16(dst + offA + i * 16, sA + i * 16);
        }
#pragma unroll
        for (int i = 0; i < 4; i++) cp16(dst + offB1 + i * 16, sB + i * 16);
#pragma unroll
        for (int i = 0; i < 4; i++) cp16(dst + offB2 + i * 16, sB + (size_t)128 * 8192 + i * 16);
    };

    uint32_t a[2][2][4];
    uint32_t b[2][8][2];

    auto load_frags = [&](int buf, uint32_t st, int kk) {
#pragma unroll
        for (int i = 0; i < 2; i++)
            ldsm_x4(a[buf][i][0], a[buf][i][1], a[buf][i][2], a[buf][i][3],
                    st + baseA + i * (16 * LDS_PADH) + kk * 32);
#pragma unroll
        for (int j2 = 0; j2 < 4; j2++) {
            uint32_t q0, q1, q2, q3;
            ldsm_x4(q0, q1, q2, q3,
                    st + baseB + j2 * (16 * LDS_PADH) + kk * 32);
            b[buf][2 * j2][0] = q0; b[buf][2 * j2 + 1][0] = q1;
            b[buf][2 * j2][1] = q2; b[buf][2 * j2 + 1][1] = q3;
        }
    };

#pragma unroll
    for (int c = 0; c < 3; c++) { load_stage(c, c); cp_commit(); }
    cp_wait1();
    __syncthreads();
    load_frags(0, sbase, 0);

    for (int c = 0; c < 64; c++) {
        cp_wait1();
        __syncthreads();

        const int kn = c + 3;
        if (kn < 64) load_stage(kn & 3, kn);
        cp_commit();

        const uint32_t stC  = sbase + (c & 3) * STAGER;
        const uint32_t stC1 = sbase + ((c + 1) & 3) * STAGER;

#pragma unroll
        for (int kk = 0; kk < 4; kk++) {
            const int cur = kk & 1;
            const int nxt = cur ^ 1;
            if (kk < 3)        load_frags(nxt, stC, kk + 1);
            else if (c < 63)   load_frags(nxt, stC1, 0);
#pragma unroll
            for (int i = 0; i < 2; i++)
#pragma unroll
                for (int j = 0; j < 8; j++)
                    mma_bf16(acc[i][j], a[cur][i][0], a[cur][i][1],
                             a[cur][i][2], a[cur][i][3],
                             b[cur][j][0], b[cur][j][1]);
        }
    }

    const float alpha = g_alpha_out;
    const int rq = lane >> 2;
    const int cq = (lane & 3) * 2;
    const int nwcol = n0 + warpN * 64 + cq;
#pragma unroll
    for (int i = 0; i < 2; i++) {
        const int row = m0 + warpM * 32 + i * 16 + rq;
        const float s0 = g_scales[row] * alpha;
        const float s1 = g_scales[row + 8] * alpha;
        float* o0 = out + (size_t)row * 4096 + nwcol;
        float* o1 = o0 + (size_t)8 * 4096;
#pragma unroll
        for (int j = 0; j < 8; j++) {
            float2 v0; v0.x = acc[i][j][0] * s0; v0.y = acc[i][j][1] * s0;
            *reinterpret_cast<float2*>(o0 + j * 8) = v0;
            float2 v1; v1.x = acc[i][j][2] * s1; v1.y = acc[i][j][3] * s1;
            *reinterpret_cast<float2*>(o1 + j * 8) = v1;
        }
    }
}

// ---------------- launch -----------------------------------------------------
extern "C" void kernel_launch(void* const* d_in, const int* in_sizes, int n_in,
                              void* d_out, int out_size) {
    (void)in_sizes; (void)n_in; (void)out_size;
    const float* x  = reinterpret_cast<const float*>(d_in[0]);
    const float* w  = reinterpret_cast<const float*>(d_in[1]);
    const float* nw = reinterpret_cast<const float*>(d_in[2]);
    float* y = reinterpret_cast<float*>(d_out);

    static bool attr_set = false;
    if (!attr_set) {
        cudaFuncSetAttribute(k_gemm_big, cudaFuncAttributeMaxDynamicSharedMemorySize, SMEMH);
        cudaFuncSetAttribute(k_gemm_rem, cudaFuncAttributeMaxDynamicSharedMemorySize, SMEMR);
        attr_set = true;
    }

    k_abs_partial<<<256, 256>>>(reinterpret_cast<const float4*>(w));
    k_quant<<<20480, 256>>>(reinterpret_cast<const float4*>(w), x, nw);
    k_gemm_big<<<BIG_TILES, 256, SMEMH>>>(y);        // 444 tiles = 3 clean waves
    k_gemm_rem<<<136, 256, SMEMR>>>(y);              // 68 tiles as 136 M-halves
}

// round 14
// speedup vs baseline: 1.0071x; 1.0071x over previous
#include <cuda_runtime.h>
#include <cuda_bf16.h>
#include <cstdint>

#define DINLINE __device__ __forceinline__

// ---------------- scratch (device globals; no runtime allocation) ----------
__device__ float g_partial[256];
__device__ float g_scales[4096];                          // gamma/127 per token
__device__ float g_alpha_out;
__device__ __align__(128) __nv_bfloat16 g_wqh[16777216];  // W ternary bf16 [N,K]
__device__ __align__(128) __nv_bfloat16 g_xqh[16777216];  // x quant  bf16 [M,K]

// ---------------- PTX helpers (baseline ISA only) ---------------------------
DINLINE uint32_t smem_u32(const void* p) {
    uint32_t a;
    asm("{ .reg .u64 t; cvta.to.shared.u64 t, %1; cvt.u32.u64 %0, t; }"
        : "=r"(a) : "l"(p));
    return a;
}
DINLINE void cp16(uint32_t dst, const void* src) {
    asm volatile("cp.async.cg.shared.global [%0], [%1], 16;" :: "r"(dst), "l"(src));
}
DINLINE void cp_commit() { asm volatile("cp.async.commit_group;" ::: "memory"); }
DINLINE void cp_wait1()  { asm volatile("cp.async.wait_group 1;" ::: "memory"); }

DINLINE void ldsm_x4(uint32_t& r0, uint32_t& r1, uint32_t& r2, uint32_t& r3, uint32_t addr) {
    asm volatile("ldmatrix.sync.aligned.m8n8.x4.shared.b16 {%0,%1,%2,%3}, [%4];"
                 : "=r"(r0), "=r"(r1), "=r"(r2), "=r"(r3) : "r"(addr));
}
DINLINE void mma_bf16(float* c, uint32_t a0, uint32_t a1, uint32_t a2, uint32_t a3,
                      uint32_t b0, uint32_t b1) {
    asm volatile(
        "mma.sync.aligned.m16n8k16.row.col.f32.bf16.bf16.f32 "
        "{%0,%1,%2,%3}, {%4,%5,%6,%7}, {%8,%9}, {%0,%1,%2,%3};"
        : "+f"(c[0]), "+f"(c[1]), "+f"(c[2]), "+f"(c[3])
        : "r"(a0), "r"(a1), "r"(a2), "r"(a3), "r"(b0), "r"(b1));
}
DINLINE int clampi(int v, int lo, int hi) { return v < lo ? lo : (v > hi ? hi : v); }
DINLINE uint32_t pack_bf16(float a, float b) {
    __nv_bfloat162 h;
    h.x = __float2bfloat16(a);
    h.y = __float2bfloat16(b);
    return *reinterpret_cast<uint32_t*>(&h);
}

// ---------------- kernel 1: |W| partial sums ---------------------------------
__global__ void __launch_bounds__(256) k_abs_partial(const float4* __restrict__ w) {
    __shared__ float red[256];
    const int b = blockIdx.x, t = threadIdx.x;
    const float4* p = w + (size_t)b * 16384;
    float s = 0.f;
#pragma unroll 8
    for (int i = 0; i < 64; i++) {
        float4 v = p[t + 256 * i];
        s += fabsf(v.x) + fabsf(v.y) + fabsf(v.z) + fabsf(v.w);
    }
    red[t] = s; __syncthreads();
#pragma unroll
    for (int o = 128; o > 0; o >>= 1) { if (t < o) red[t] += red[t + o]; __syncthreads(); }
    if (t == 0) g_partial[b] = red[0];
}

// ---------------- kernel 2: merged quantization ------------------------------
// Blocks [0,16384): finalize alpha per-block + ternary-quantize W -> bf16.
// Blocks [16384,20480): RMSNorm + int8-grid quantize one x row -> bf16.
// g_scales stores gamma/127 only; GEMM epilogues multiply by g_alpha_out.
__global__ void __launch_bounds__(256) k_quant(const float4* __restrict__ w,
                                               const float* __restrict__ x,
                                               const float* __restrict__ nw) {
    __shared__ float red[256];
    const int t = threadIdx.x;

    if (blockIdx.x < 16384) {
        // ---- W path ----
        red[t] = g_partial[t]; __syncthreads();
#pragma unroll
        for (int o = 128; o > 0; o >>= 1) { if (t < o) red[t] += red[t + o]; __syncthreads(); }
        const float alpha = fmaxf(red[0] * (1.0f / 16777216.0f), 1e-10f);
        if (blockIdx.x == 0 && t == 0) g_alpha_out = alpha;
        const float inv_alpha = 1.0f / alpha;

        const int idx = blockIdx.x * 256 + t;      // float4 index, 4194304 total
        float4 v = w[idx];
        int q0 = clampi(__float2int_rn(v.x * inv_alpha), -1, 1);
        int q1 = clampi(__float2int_rn(v.y * inv_alpha), -1, 1);
        int q2 = clampi(__float2int_rn(v.z * inv_alpha), -1, 1);
        int q3 = clampi(__float2int_rn(v.w * inv_alpha), -1, 1);
        uint2 h;
        h.x = pack_bf16((float)q0, (float)q1);
        h.y = pack_bf16((float)q2, (float)q3);
        reinterpret_cast<uint2*>(g_wqh)[idx] = h;
        return;
    }

    // ---- x path ----
    const int m = blockIdx.x - 16384;
    const float4* xr = reinterpret_cast<const float4*>(x + (size_t)m * 4096);
    const float4* nwr = reinterpret_cast<const float4*>(nw);

    float4 v[4], g[4];
    float ss = 0.f;
#pragma unroll
    for (int i = 0; i < 4; i++) {
        v[i] = xr[t + 256 * i];
        g[i] = nwr[t + 256 * i];
        ss += v[i].x * v[i].x + v[i].y * v[i].y + v[i].z * v[i].z + v[i].w * v[i].w;
    }
    red[t] = ss; __syncthreads();
#pragma unroll
    for (int o = 128; o > 0; o >>= 1) { if (t < o) red[t] += red[t + o]; __syncthreads(); }
    const float rinv = 1.0f / sqrtf(red[0] * (1.0f / 4096.0f) + 1e-6f);
    __syncthreads();

    float mx = 0.f;
#pragma unroll
    for (int i = 0; i < 4; i++) {
        v[i].x *= rinv * g[i].x; v[i].y *= rinv * g[i].y;
        v[i].z *= rinv * g[i].z; v[i].w *= rinv * g[i].w;
        mx = fmaxf(mx, fmaxf(fmaxf(fabsf(v[i].x), fabsf(v[i].y)),
                             fmaxf(fabsf(v[i].z), fabsf(v[i].w))));
    }
    red[t] = mx; __syncthreads();
#pragma unroll
    for (int o = 128; o > 0; o >>= 1) { if (t < o) red[t] = fmaxf(red[t], red[t + o]); __syncthreads(); }
    const float gamma = fmaxf(red[0], 1e-10f);
    if (t == 0) g_scales[m] = gamma * (1.0f / 127.0f);   // alpha applied in epilogue
    const float qs = 127.0f / gamma;
    uint2* dsth = reinterpret_cast<uint2*>(g_xqh) + (size_t)m * 1024;
#pragma unroll
    for (int i = 0; i < 4; i++) {
        int q0 = clampi(__float2int_rn(v[i].x * qs), -128, 127);
        int q1 = clampi(__float2int_rn(v[i].y * qs), -128, 127);
        int q2 = clampi(__float2int_rn(v[i].z * qs), -128, 127);
        int q3 = clampi(__float2int_rn(v[i].w * qs), -128, 127);
        uint2 h;
        h.x = pack_bf16((float)q0, (float)q1);
        h.y = pack_bf16((float)q2, (float)q3);
        dsth[t + 256 * i] = h;
    }
}

// Tile numbering: big-tile id T in [0,512): n0 = (T & 15)*256, m0 = (T >> 4)*128.
// Big kernel: T in [0,444) = exactly 3 clean waves of 148.
// Rem kernel: T in [444,512) as 136 N-split 128x128 tiles, 4 warps of 64x64.
static constexpr int BIG_TILES = 444;

static constexpr int LDS_PADH = 144;

// ================= GEMM big: 128x256 tile, 8 warps of 64x64 (R12 body) ======
static constexpr int A_SZ   = 128 * LDS_PADH;        // 18432
static constexpr int B_SZ   = 256 * LDS_PADH;        // 36864
static constexpr int STAGEH = A_SZ + B_SZ;           // 55296
static constexpr int SMEMH  = 4 * STAGEH;            // 221184

__global__ void __launch_bounds__(256, 1) k_gemm_big(float* __restrict__ out) {
    extern __shared__ char smemraw[];
    const uint32_t sbase = smem_u32(smemraw);
    const int t = threadIdx.x;
    const int lane = t & 31, wid = t >> 5;
    const int warpM = wid >> 2;          // 0..1  -> 64-row M slab
    const int warpN = wid & 3;           // 0..3  -> 64-col N slab
    const int T = blockIdx.x;
    const int m0 = (T >> 4) * 128, n0 = (T & 15) * 256;

    const char* gA = reinterpret_cast<const char*>(g_xqh) + (size_t)m0 * 8192;
    const char* gB = reinterpret_cast<const char*>(g_wqh) + (size_t)n0 * 8192;

    const int lr = t >> 1;               // 0..127
    const int lc = (t & 1) * 64;         // 0 or 64
    const char* pA = gA + (size_t)lr * 8192 + lc;
    const char* pB = gB + (size_t)lr * 8192 + lc;
    const uint32_t offA  = (uint32_t)(lr * LDS_PADH + lc);
    const uint32_t offB1 = (uint32_t)(A_SZ + lr * LDS_PADH + lc);
    const uint32_t offB2 = offB1 + 128 * LDS_PADH;

    const int xrow = (lane & 7) + ((lane >> 3) & 1) * 8;
    const int xcol = (lane >> 4) * 16;
    const uint32_t baseA = (uint32_t)((warpM * 64 + xrow) * LDS_PADH + xcol);
    const uint32_t baseB = (uint32_t)(A_SZ + (warpN * 64 + xrow) * LDS_PADH + xcol);

    float acc[4][8][4];
#pragma unroll
    for (int i = 0; i < 4; i++)
#pragma unroll
        for (int j = 0; j < 8; j++)
#pragma unroll
            for (int q = 0; q < 4; q++) acc[i][j][q] = 0.f;

    auto load_stage = [&](int s, int c) {
        const uint32_t dst = sbase + s * STAGEH;
        const char* sA = pA + (size_t)c * 128;
        const char* sB = pB + (size_t)c * 128;
#pragma unroll
        for (int i = 0; i < 4; i++) cp16(dst + offA  + i * 16, sA + i * 16);
#pragma unroll
        for (int i = 0; i < 4; i++) cp16(dst + offB1 + i * 16, sB + i * 16);
#pragma unroll
        for (int i = 0; i < 4; i++) cp16(dst + offB2 + i * 16, sB + (size_t)128 * 8192 + i * 16);
    };

    uint32_t a[2][4][4];
    uint32_t b[2][8][2];

    auto load_frags = [&](int buf, uint32_t st, int kk) {
#pragma unroll
        for (int i = 0; i < 4; i++)
            ldsm_x4(a[buf][i][0], a[buf][i][1], a[buf][i][2], a[buf][i][3],
                    st + baseA + i * (16 * LDS_PADH) + kk * 32);
#pragma unroll
        for (int j2 = 0; j2 < 4; j2++) {
            uint32_t q0, q1, q2, q3;
            ldsm_x4(q0, q1, q2, q3,
                    st + baseB + j2 * (16 * LDS_PADH) + kk * 32);
            b[buf][2 * j2][0] = q0; b[buf][2 * j2 + 1][0] = q1;
            b[buf][2 * j2][1] = q2; b[buf][2 * j2 + 1][1] = q3;
        }
    };

#pragma unroll
    for (int c = 0; c < 3; c++) { load_stage(c, c); cp_commit(); }
    cp_wait1();
    __syncthreads();
    load_frags(0, sbase, 0);

    for (int c = 0; c < 64; c++) {
        cp_wait1();
        __syncthreads();

        const int kn = c + 3;
        if (kn < 64) load_stage(kn & 3, kn);
        cp_commit();

        const uint32_t stC  = sbase + (c & 3) * STAGEH;
        const uint32_t stC1 = sbase + ((c + 1) & 3) * STAGEH;

#pragma unroll
        for (int kk = 0; kk < 4; kk++) {
            const int cur = kk & 1;
            const int nxt = cur ^ 1;
            if (kk < 3)        load_frags(nxt, stC, kk + 1);
            else if (c < 63)   load_frags(nxt, stC1, 0);
#pragma unroll
            for (int i = 0; i < 4; i++)
#pragma unroll
                for (int j = 0; j < 8; j++)
                    mma_bf16(acc[i][j], a[cur][i][0], a[cur][i][1],
                             a[cur][i][2], a[cur][i][3],
                             b[cur][j][0], b[cur][j][1]);
        }
    }

    const float alpha = g_alpha_out;
    const int rq = lane >> 2;
    const int cq = (lane & 3) * 2;
    const int nwcol = n0 + warpN * 64 + cq;
#pragma unroll
    for (int i = 0; i < 4; i++) {
        const int row = m0 + warpM * 64 + i * 16 + rq;
        const float s0 = g_scales[row] * alpha;
        const float s1 = g_scales[row + 8] * alpha;
        float* o0 = out + (size_t)row * 4096 + nwcol;
        float* o1 = o0 + (size_t)8 * 4096;
#pragma unroll
        for (int j = 0; j < 8; j++) {
            float2 v0; v0.x = acc[i][j][0] * s0; v0.y = acc[i][j][1] * s0;
            *reinterpret_cast<float2*>(o0 + j * 8) = v0;
            float2 v1; v1.x = acc[i][j][2] * s1; v1.y = acc[i][j][3] * s1;
            *reinterpret_cast<float2*>(o1 + j * 8) = v1;
        }
    }
}

// ================= GEMM rem: 128x128 tile, 4 warps of 64x64 =================
// Same warp shape as the big body (demand-bound MMA:ldsm ratio), 1 warp/SMSP.
// Per-chunk demand: 512 MMAs / 4 SMSP * rt16 = 2048 cyc -> ~73 us per tile.
static constexpr int AR_SZ   = 128 * LDS_PADH;       // 18432
static constexpr int STAGER  = 2 * AR_SZ;            // 36864
static constexpr int SMEMR   = 4 * STAGER;           // 147456

__global__ void __launch_bounds__(128, 1) k_gemm_rem(float* __restrict__ out) {
    extern __shared__ char smemraw[];
    const uint32_t sbase = smem_u32(smemraw);
    const int t = threadIdx.x;
    const int lane = t & 31, wid = t >> 5;   // wid 0..3
    const int warpM = wid >> 1;              // 0..1 -> 64-row M slab
    const int warpN = wid & 1;               // 0..1 -> 64-col N slab
    const int S = blockIdx.x;                // 0..135
    const int T = BIG_TILES + (S >> 1);
    const int m0 = (T >> 4) * 128;
    const int n0 = (T & 15) * 256 + (S & 1) * 128;

    const char* gA = reinterpret_cast<const char*>(g_xqh) + (size_t)m0 * 8192;
    const char* gB = reinterpret_cast<const char*>(g_wqh) + (size_t)n0 * 8192;

    // loader: 1 thread per 128B row; 8 cp16 for its A row, 8 for its B row
    const int lr = t;                        // 0..127
    const char* pA = gA + (size_t)lr * 8192;
    const char* pB = gB + (size_t)lr * 8192;
    const uint32_t offA = (uint32_t)(lr * LDS_PADH);
    const uint32_t offB = offA + AR_SZ;

    const int xrow = (lane & 7) + ((lane >> 3) & 1) * 8;
    const int xcol = (lane >> 4) * 16;
    const uint32_t baseA = (uint32_t)((warpM * 64 + xrow) * LDS_PADH + xcol);
    const uint32_t baseB = (uint32_t)(AR_SZ + (warpN * 64 + xrow) * LDS_PADH + xcol);

    float acc[4][8][4];
#pragma unroll
    for (int i = 0; i < 4; i++)
#pragma unroll
        for (int j = 0; j < 8; j++)
#pragma unroll
            for (int q = 0; q < 4; q++) acc[i][j][q] = 0.f;

    auto load_stage = [&](int s, int c) {
        const uint32_t dst = sbase + s * STAGER;
        const char* sA = pA + (size_t)c * 128;
        const char* sB = pB + (size_t)c * 128;
#pragma unroll
        for (int i = 0; i < 8; i++) cp16(dst + offA + i * 16, sA + i * 16);
#pragma unroll
        for (int i = 0; i < 8; i++) cp16(dst + offB + i * 16, sB + i * 16);
    };

    uint32_t a[2][4][4];
    uint32_t b[2][8][2];

    auto load_frags = [&](int buf, uint32_t st, int kk) {
#pragma unroll
        for (int i = 0; i < 4; i++)
            ldsm_x4(a[buf][i][0], a[buf][i][1], a[buf][i][2], a[buf][i][3],
                    st + baseA + i * (16 * LDS_PADH) + kk * 32);
#pragma unroll
        for (int j2 = 0; j2 < 4; j2++) {
            uint32_t q0, q1, q2, q3;
            ldsm_x4(q0, q1, q2, q3,
                    st + baseB + j2 * (16 * LDS_PADH) + kk * 32);
            b[buf][2 * j2][0] = q0; b[buf][2 * j2 + 1][0] = q1;
            b[buf][2 * j2][1] = q2; b[buf][2 * j2 + 1][1] = q3;
        }
    };

#pragma unroll
    for (int c = 0; c < 3; c++) { load_stage(c, c); cp_commit(); }
    cp_wait1();
    __syncthreads();
    load_frags(0, sbase, 0);

    for (int c = 0; c < 64; c++) {
        cp_wait1();
        __syncthreads();

        const int kn = c + 3;
        if (kn < 64) load_stage(kn & 3, kn);
        cp_commit();

        const uint32_t stC  = sbase + (c & 3) * STAGER;
        const uint32_t stC1 = sbase + ((c + 1) & 3) * STAGER;

#pragma unroll
        for (int kk = 0; kk < 4; kk++) {
            const int cur = kk & 1;
            const int nxt = cur ^ 1;
            if (kk < 3)        load_frags(nxt, stC, kk + 1);
            else if (c < 63)   load_frags(nxt, stC1, 0);
#pragma unroll
            for (int i = 0; i < 4; i++)
#pragma unroll
                for (int j = 0; j < 8; j++)
                    mma_bf16(acc[i][j], a[cur][i][0], a[cur][i][1],
                             a[cur][i][2], a[cur][i][3],
                             b[cur][j][0], b[cur][j][1]);
        }
    }

    const float alpha = g_alpha_out;
    const int rq = lane >> 2;
    const int cq = (lane & 3) * 2;
    const int nwcol = n0 + warpN * 64 + cq;
#pragma unroll
    for (int i = 0; i < 4; i++) {
        const int row = m0 + warpM * 64 + i * 16 + rq;
        const float s0 = g_scales[row] * alpha;
        const float s1 = g_scales[row + 8] * alpha;
        float* o0 = out + (size_t)row * 4096 + nwcol;
        float* o1 = o0 + (size_t)8 * 4096;
#pragma unroll
        for (int j = 0; j < 8; j++) {
            float2 v0; v0.x = acc[i][j][0] * s0; v0.y = acc[i][j][1] * s0;
            *reinterpret_cast<float2*>(o0 + j * 8) = v0;
            float2 v1; v1.x = acc[i][j][2] * s1; v1.y = acc[i][j][3] * s1;
            *reinterpret_cast<float2*>(o1 + j * 8) = v1;
        }
    }
}

// ---------------- launch -----------------------------------------------------
extern "C" void kernel_launch(void* const* d_in, const int* in_sizes, int n_in,
                              void* d_out, int out_size) {
    (void)in_sizes; (void)n_in; (void)out_size;
    const float* x  = reinterpret_cast<const float*>(d_in[0]);
    const float* w  = reinterpret_cast<const float*>(d_in[1]);
    const float* nw = reinterpret_cast<const float*>(d_in[2]);
    float* y = reinterpret_cast<float*>(d_out);

    static bool attr_set = false;
    if (!attr_set) {
        cudaFuncSetAttribute(k_gemm_big, cudaFuncAttributeMaxDynamicSharedMemorySize, SMEMH);
        cudaFuncSetAttribute(k_gemm_rem, cudaFuncAttributeMaxDynamicSharedMemorySize, SMEMR);
        attr_set = true;
    }

    k_abs_partial<<<256, 256>>>(reinterpret_cast<const float4*>(w));
    k_quant<<<20480, 256>>>(reinterpret_cast<const float4*>(w), x, nw);
    k_gemm_big<<<BIG_TILES, 256, SMEMH>>>(y);        // 444 tiles = 3 clean waves
    k_gemm_rem<<<136, 128, SMEMR>>>(y);              // 68 tiles as 136 N-halves
}

// round 15
// speedup vs baseline: 1.0163x; 1.0091x over previous
#include <cuda_runtime.h>
#include <cuda_bf16.h>
#include <cstdint>

#define DINLINE __device__ __forceinline__

// ---------------- scratch (device globals; no runtime allocation) ----------
__device__ float g_partial[256];
__device__ float g_scales[4096];                          // gamma/127 per token
__device__ float g_alpha_out;
__device__ __align__(128) __nv_bfloat16 g_wqh[16777216];  // W ternary bf16 [N,K]
__device__ __align__(128) __nv_bfloat16 g_xqh[16777216];  // x quant  bf16 [M,K]

// ---------------- PTX helpers (baseline ISA only) ---------------------------
DINLINE uint32_t smem_u32(const void* p) {
    uint32_t a;
    asm("{ .reg .u64 t; cvta.to.shared.u64 t, %1; cvt.u32.u64 %0, t; }"
        : "=r"(a) : "l"(p));
    return a;
}
DINLINE void cp16(uint32_t dst, const void* src) {
    asm volatile("cp.async.cg.shared.global [%0], [%1], 16;" :: "r"(dst), "l"(src));
}
DINLINE void cp_commit() { asm volatile("cp.async.commit_group;" ::: "memory"); }
DINLINE void cp_wait1()  { asm volatile("cp.async.wait_group 1;" ::: "memory"); }

DINLINE void ldsm_x4(uint32_t& r0, uint32_t& r1, uint32_t& r2, uint32_t& r3, uint32_t addr) {
    asm volatile("ldmatrix.sync.aligned.m8n8.x4.shared.b16 {%0,%1,%2,%3}, [%4];"
                 : "=r"(r0), "=r"(r1), "=r"(r2), "=r"(r3) : "r"(addr));
}
DINLINE void mma_bf16(float* c, uint32_t a0, uint32_t a1, uint32_t a2, uint32_t a3,
                      uint32_t b0, uint32_t b1) {
    asm volatile(
        "mma.sync.aligned.m16n8k16.row.col.f32.bf16.bf16.f32 "
        "{%0,%1,%2,%3}, {%4,%5,%6,%7}, {%8,%9}, {%0,%1,%2,%3};"
        : "+f"(c[0]), "+f"(c[1]), "+f"(c[2]), "+f"(c[3])
        : "r"(a0), "r"(a1), "r"(a2), "r"(a3), "r"(b0), "r"(b1));
}
DINLINE int clampi(int v, int lo, int hi) { return v < lo ? lo : (v > hi ? hi : v); }
DINLINE uint32_t pack_bf16(float a, float b) {
    __nv_bfloat162 h;
    h.x = __float2bfloat16(a);
    h.y = __float2bfloat16(b);
    return *reinterpret_cast<uint32_t*>(&h);
}

// ---------------- kernel 1: x RMSNorm+quant  MERGED WITH  |W| partial sums ---
// Blocks [0,4096): RMSNorm + int8-grid quantize one x row -> bf16 (g_scales=gamma/127).
// Blocks [4096,4352): |W| partial sums into g_partial (independent of x path).
__global__ void __launch_bounds__(256) k_pre(const float4* __restrict__ w,
                                             const float* __restrict__ x,
                                             const float* __restrict__ nw) {
    __shared__ float red[256];
    const int t = threadIdx.x;

    if (blockIdx.x >= 4096) {
        // ---- |W| partial sums ----
        const int b = blockIdx.x - 4096;
        const float4* p = w + (size_t)b * 16384;
        float s = 0.f;
#pragma unroll 8
        for (int i = 0; i < 64; i++) {
            float4 v = p[t + 256 * i];
            s += fabsf(v.x) + fabsf(v.y) + fabsf(v.z) + fabsf(v.w);
        }
        red[t] = s; __syncthreads();
#pragma unroll
        for (int o = 128; o > 0; o >>= 1) { if (t < o) red[t] += red[t + o]; __syncthreads(); }
        if (t == 0) g_partial[b] = red[0];
        return;
    }

    // ---- x path ----
    const int m = blockIdx.x;
    const float4* xr = reinterpret_cast<const float4*>(x + (size_t)m * 4096);
    const float4* nwr = reinterpret_cast<const float4*>(nw);

    float4 v[4], g[4];
    float ss = 0.f;
#pragma unroll
    for (int i = 0; i < 4; i++) {
        v[i] = xr[t + 256 * i];
        g[i] = nwr[t + 256 * i];
        ss += v[i].x * v[i].x + v[i].y * v[i].y + v[i].z * v[i].z + v[i].w * v[i].w;
    }
    red[t] = ss; __syncthreads();
#pragma unroll
    for (int o = 128; o > 0; o >>= 1) { if (t < o) red[t] += red[t + o]; __syncthreads(); }
    const float rinv = 1.0f / sqrtf(red[0] * (1.0f / 4096.0f) + 1e-6f);
    __syncthreads();

    float mx = 0.f;
#pragma unroll
    for (int i = 0; i < 4; i++) {
        v[i].x *= rinv * g[i].x; v[i].y *= rinv * g[i].y;
        v[i].z *= rinv * g[i].z; v[i].w *= rinv * g[i].w;
        mx = fmaxf(mx, fmaxf(fmaxf(fabsf(v[i].x), fabsf(v[i].y)),
                             fmaxf(fabsf(v[i].z), fabsf(v[i].w))));
    }
    red[t] = mx; __syncthreads();
#pragma unroll
    for (int o = 128; o > 0; o >>= 1) { if (t < o) red[t] = fmaxf(red[t], red[t + o]); __syncthreads(); }
    const float gamma = fmaxf(red[0], 1e-10f);
    if (t == 0) g_scales[m] = gamma * (1.0f / 127.0f);   // alpha applied in epilogue
    const float qs = 127.0f / gamma;
    uint2* dsth = reinterpret_cast<uint2*>(g_xqh) + (size_t)m * 1024;
#pragma unroll
    for (int i = 0; i < 4; i++) {
        int q0 = clampi(__float2int_rn(v[i].x * qs), -128, 127);
        int q1 = clampi(__float2int_rn(v[i].y * qs), -128, 127);
        int q2 = clampi(__float2int_rn(v[i].z * qs), -128, 127);
        int q3 = clampi(__float2int_rn(v[i].w * qs), -128, 127);
        uint2 h;
        h.x = pack_bf16((float)q0, (float)q1);
        h.y = pack_bf16((float)q2, (float)q3);
        dsth[t + 256 * i] = h;
    }
}

// ---------------- kernel 2: finalize alpha + ternary quantize W -> bf16 -----
__global__ void __launch_bounds__(256) k_quant_w(const float4* __restrict__ w) {
    __shared__ float red[256];
    const int t = threadIdx.x;
    red[t] = g_partial[t]; __syncthreads();
#pragma unroll
    for (int o = 128; o > 0; o >>= 1) { if (t < o) red[t] += red[t + o]; __syncthreads(); }
    const float alpha = fmaxf(red[0] * (1.0f / 16777216.0f), 1e-10f);
    if (blockIdx.x == 0 && t == 0) g_alpha_out = alpha;
    const float inv_alpha = 1.0f / alpha;

    const int idx = blockIdx.x * 256 + t;          // float4 index, 4194304 total
    float4 v = w[idx];
    int q0 = clampi(__float2int_rn(v.x * inv_alpha), -1, 1);
    int q1 = clampi(__float2int_rn(v.y * inv_alpha), -1, 1);
    int q2 = clampi(__float2int_rn(v.z * inv_alpha), -1, 1);
    int q3 = clampi(__float2int_rn(v.w * inv_alpha), -1, 1);
    uint2 h;
    h.x = pack_bf16((float)q0, (float)q1);
    h.y = pack_bf16((float)q2, (float)q3);
    reinterpret_cast<uint2*>(g_wqh)[idx] = h;
}

// Tile numbering: big-tile id T in [0,512): n0 = (T & 15)*256, m0 = (T >> 4)*128.
// Big kernel: T in [0,444) = exactly 3 clean waves of 148.
// Rem kernel: T in [444,512) as 136 N-split 128x128 split-K tiles.
static constexpr int BIG_TILES = 444;

static constexpr int LDS_PADH = 144;

// ================= GEMM big: 128x256 tile, 8 warps of 64x64 (R12 body) ======
static constexpr int A_SZ   = 128 * LDS_PADH;        // 18432
static constexpr int B_SZ   = 256 * LDS_PADH;        // 36864
static constexpr int STAGEH = A_SZ + B_SZ;           // 55296
static constexpr int SMEMH  = 4 * STAGEH;            // 221184

__global__ void __launch_bounds__(256, 1) k_gemm_big(float* __restrict__ out) {
    extern __shared__ char smemraw[];
    const uint32_t sbase = smem_u32(smemraw);
    const int t = threadIdx.x;
    const int lane = t & 31, wid = t >> 5;
    const int warpM = wid >> 2;          // 0..1  -> 64-row M slab
    const int warpN = wid & 3;           // 0..3  -> 64-col N slab
    const int T = blockIdx.x;
    const int m0 = (T >> 4) * 128, n0 = (T & 15) * 256;

    const char* gA = reinterpret_cast<const char*>(g_xqh) + (size_t)m0 * 8192;
    const char* gB = reinterpret_cast<const char*>(g_wqh) + (size_t)n0 * 8192;

    const int lr = t >> 1;               // 0..127
    const int lc = (t & 1) * 64;         // 0 or 64
    const char* pA = gA + (size_t)lr * 8192 + lc;
    const char* pB = gB + (size_t)lr * 8192 + lc;
    const uint32_t offA  = (uint32_t)(lr * LDS_PADH + lc);
    const uint32_t offB1 = (uint32_t)(A_SZ + lr * LDS_PADH + lc);
    const uint32_t offB2 = offB1 + 128 * LDS_PADH;

    const int xrow = (lane & 7) + ((lane >> 3) & 1) * 8;
    const int xcol = (lane >> 4) * 16;
    const uint32_t baseA = (uint32_t)((warpM * 64 + xrow) * LDS_PADH + xcol);
    const uint32_t baseB = (uint32_t)(A_SZ + (warpN * 64 + xrow) * LDS_PADH + xcol);

    float acc[4][8][4];
#pragma unroll
    for (int i = 0; i < 4; i++)
#pragma unroll
        for (int j = 0; j < 8; j++)
#pragma unroll
            for (int q = 0; q < 4; q++) acc[i][j][q] = 0.f;

    auto load_stage = [&](int s, int c) {
        const uint32_t dst = sbase + s * STAGEH;
        const char* sA = pA + (size_t)c * 128;
        const char* sB = pB + (size_t)c * 128;
#pragma unroll
        for (int i = 0; i < 4; i++) cp16(dst + offA  + i * 16, sA + i * 16);
#pragma unroll
        for (int i = 0; i < 4; i++) cp16(dst + offB1 + i * 16, sB + i * 16);
#pragma unroll
        for (int i = 0; i < 4; i++) cp16(dst + offB2 + i * 16, sB + (size_t)128 * 8192 + i * 16);
    };

    uint32_t a[2][4][4];
    uint32_t b[2][8][2];

    auto load_frags = [&](int buf, uint32_t st, int kk) {
#pragma unroll
        for (int i = 0; i < 4; i++)
            ldsm_x4(a[buf][i][0], a[buf][i][1], a[buf][i][2], a[buf][i][3],
                    st + baseA + i * (16 * LDS_PADH) + kk * 32);
#pragma unroll
        for (int j2 = 0; j2 < 4; j2++) {
            uint32_t q0, q1, q2, q3;
            ldsm_x4(q0, q1, q2, q3,
                    st + baseB + j2 * (16 * LDS_PADH) + kk * 32);
            b[buf][2 * j2][0] = q0; b[buf][2 * j2 + 1][0] = q1;
            b[buf][2 * j2][1] = q2; b[buf][2 * j2 + 1][1] = q3;
        }
    };

#pragma unroll
    for (int c = 0; c < 3; c++) { load_stage(c, c); cp_commit(); }
    cp_wait1();
    __syncthreads();
    load_frags(0, sbase, 0);

    for (int c = 0; c < 64; c++) {
        cp_wait1();
        __syncthreads();

        const int kn = c + 3;
        if (kn < 64) load_stage(kn & 3, kn);
        cp_commit();

        const uint32_t stC  = sbase + (c & 3) * STAGEH;
        const uint32_t stC1 = sbase + ((c + 1) & 3) * STAGEH;

#pragma unroll
        for (int kk = 0; kk < 4; kk++) {
            const int cur = kk & 1;
            const int nxt = cur ^ 1;
            if (kk < 3)        load_frags(nxt, stC, kk + 1);
            else if (c < 63)   load_frags(nxt, stC1, 0);
#pragma unroll
            for (int i = 0; i < 4; i++)
#pragma unroll
                for (int j = 0; j < 8; j++)
                    mma_bf16(acc[i][j], a[cur][i][0], a[cur][i][1],
                             a[cur][i][2], a[cur][i][3],
                             b[cur][j][0], b[cur][j][1]);
        }
    }

    const float alpha = g_alpha_out;
    const int rq = lane >> 2;
    const int cq = (lane & 3) * 2;
    const int nwcol = n0 + warpN * 64 + cq;
#pragma unroll
    for (int i = 0; i < 4; i++) {
        const int row = m0 + warpM * 64 + i * 16 + rq;
        const float s0 = g_scales[row] * alpha;
        const float s1 = g_scales[row + 8] * alpha;
        float* o0 = out + (size_t)row * 4096 + nwcol;
        float* o1 = o0 + (size_t)8 * 4096;
#pragma unroll
        for (int j = 0; j < 8; j++) {
            float2 v0; v0.x = acc[i][j][0] * s0; v0.y = acc[i][j][1] * s0;
            *reinterpret_cast<float2*>(o0 + j * 8) = v0;
            float2 v1; v1.x = acc[i][j][2] * s1; v1.y = acc[i][j][3] * s1;
            *reinterpret_cast<float2*>(o1 + j * 8) = v1;
        }
    }
}

// ================= GEMM rem: 128x128 split-K, 8 warps of 64x64 ==============
// Warp groups kg in {0,1}: kg handles K-chunks [32*kg, 32*kg+32). Each group's
// 4 warps tile the full 128x128 output as 64x64 quadrants (the proven big-body
// warp shape: 32 MMAs per 6 ldsm, 2 warps/SMSP). Stages hold a chunk PAIR
// (c, c+32). Epilogue: group 1 spills fp32 partials to smem; group 0 adds,
// scales, stores. fp32 adds of integer-valued sums < 2^24 are exact.
static constexpr int SUB_SZ = 2 * 128 * LDS_PADH;    // A+B for one chunk: 36864
static constexpr int STAGEK = 2 * SUB_SZ;            // chunk pair: 73728
static constexpr int SMEMK  = 3 * STAGEK;            // 221184

__global__ void __launch_bounds__(256, 1) k_gemm_rem(float* __restrict__ out) {
    extern __shared__ char smemraw[];
    const uint32_t sbase = smem_u32(smemraw);
    const int t = threadIdx.x;
    const int lane = t & 31, wid = t >> 5;
    const int kg = wid >> 2;                 // K group 0/1
    const int wq = wid & 3;                  // quadrant within group
    const int warpM = wq >> 1, warpN = wq & 1;
    const int S = blockIdx.x;                // 0..135
    const int T = BIG_TILES + (S >> 1);
    const int m0 = (T >> 4) * 128;
    const int n0 = (T & 15) * 256 + (S & 1) * 128;

    const char* gA = reinterpret_cast<const char*>(g_xqh) + (size_t)m0 * 8192;
    const char* gB = reinterpret_cast<const char*>(g_wqh) + (size_t)n0 * 8192;

    // loader: 2 threads per 128B row; each sub-stage: A row lr + B row lr
    const int lr = t >> 1;                   // 0..127
    const int lc = (t & 1) * 64;
    const char* pA = gA + (size_t)lr * 8192 + lc;
    const char* pB = gB + (size_t)lr * 8192 + lc;
    const uint32_t offA = (uint32_t)(lr * LDS_PADH + lc);
    const uint32_t offB = offA + 128 * LDS_PADH;     // B region within sub

    const int xrow = (lane & 7) + ((lane >> 3) & 1) * 8;
    const int xcol = (lane >> 4) * 16;
    const uint32_t baseA = (uint32_t)((warpM * 64 + xrow) * LDS_PADH + xcol);
    const uint32_t baseB = (uint32_t)(128 * LDS_PADH + (warpN * 64 + xrow) * LDS_PADH + xcol);
    const uint32_t suboff = (uint32_t)kg * SUB_SZ;

    float acc[4][8][4];
#pragma unroll
    for (int i = 0; i < 4; i++)
#pragma unroll
        for (int j = 0; j < 8; j++)
#pragma unroll
            for (int q = 0; q < 4; q++) acc[i][j][q] = 0.f;

    // stage s <- chunk pair (c, c+32)
    auto load_stage = [&](int s, int c) {
        const uint32_t dst = sbase + s * STAGEK;
#pragma unroll
        for (int s2 = 0; s2 < 2; s2++) {
            const char* sA = pA + (size_t)(c + 32 * s2) * 128;
            const char* sB = pB + (size_t)(c + 32 * s2) * 128;
            const uint32_t d = dst + s2 * SUB_SZ;
#pragma unroll
            for (int i = 0; i < 4; i++) cp16(d + offA + i * 16, sA + i * 16);
#pragma unroll
            for (int i = 0; i < 4; i++) cp16(d + offB + i * 16, sB + i * 16);
        }
    };

    uint32_t a[2][4][4];
    uint32_t b[2][8][2];

    auto load_frags = [&](int buf, uint32_t st, int kk) {
#pragma unroll
        for (int i = 0; i < 4; i++)
            ldsm_x4(a[buf][i][0], a[buf][i][1], a[buf][i][2], a[buf][i][3],
                    st + baseA + i * (16 * LDS_PADH) + kk * 32);
#pragma unroll
        for (int j2 = 0; j2 < 4; j2++) {
            uint32_t q0, q1, q2, q3;
            ldsm_x4(q0, q1, q2, q3,
                    st + baseB + j2 * (16 * LDS_PADH) + kk * 32);
            b[buf][2 * j2][0] = q0; b[buf][2 * j2 + 1][0] = q1;
            b[buf][2 * j2][1] = q2; b[buf][2 * j2 + 1][1] = q3;
        }
    };

    // prologue: pairs 0,1 into stages 0,1 (groups 0,1)
#pragma unroll
    for (int c = 0; c < 2; c++) { load_stage(c, c); cp_commit(); }

    for (int c = 0; c < 32; c++) {
        // committed groups so far: 0..c+1 (pairs 0..c+1). wait1 -> pairs 0..c
        // resident; barrier -> visible. Stage (c+2)%3 held pair c-1, whose
        // reads finished last iteration -> safe to refill.
        cp_wait1();
        __syncthreads();

        const int kn = c + 2;
        if (kn < 32) load_stage(kn % 3, kn);
        cp_commit();

        const uint32_t stC = sbase + (c % 3) * STAGEK + suboff;
        load_frags(0, stC, 0);       // non-overlapped first frag (1 of 4)

#pragma unroll
        for (int kk = 0; kk < 4; kk++) {
            const int cur = kk & 1;
            if (kk < 3) load_frags(cur ^ 1, stC, kk + 1);
#pragma unroll
            for (int i = 0; i < 4; i++)
#pragma unroll
                for (int j = 0; j < 8; j++)
                    mma_bf16(acc[i][j], a[cur][i][0], a[cur][i][1],
                             a[cur][i][2], a[cur][i][3],
                             b[cur][j][0], b[cur][j][1]);
        }
    }

    // ---- split-K reduction + scaled store ----
    __syncthreads();                 // all MMAs done; stage smem reusable
    float* sh = reinterpret_cast<float*>(smemraw);
    const int sbaseidx = (wq * 32 + lane) * 128;
    if (kg == 1) {
#pragma unroll
        for (int i = 0; i < 4; i++)
#pragma unroll
            for (int j = 0; j < 8; j++)
#pragma unroll
                for (int q = 0; q < 4; q++)
                    sh[sbaseidx + (i * 8 + j) * 4 + q] = acc[i][j][q];
    }
    __syncthreads();
    if (kg == 0) {
        const float alpha = g_alpha_out;
        const int rq = lane >> 2;
        const int cq = (lane & 3) * 2;
        const int nwcol = n0 + warpN * 64 + cq;
#pragma unroll
        for (int i = 0; i < 4; i++) {
            const int row = m0 + warpM * 64 + i * 16 + rq;
            const float s0 = g_scales[row] * alpha;
            const float s1 = g_scales[row + 8] * alpha;
            float* o0 = out + (size_t)row * 4096 + nwcol;
            float* o1 = o0 + (size_t)8 * 4096;
#pragma unroll
            for (int j = 0; j < 8; j++) {
                const int e = sbaseidx + (i * 8 + j) * 4;
                float2 v0;
                v0.x = (acc[i][j][0] + sh[e + 0]) * s0;
                v0.y = (acc[i][j][1] + sh[e + 1]) * s0;
                *reinterpret_cast<float2*>(o0 + j * 8) = v0;
                float2 v1;
                v1.x = (acc[i][j][2] + sh[e + 2]) * s1;
                v1.y = (acc[i][j][3] + sh[e + 3]) * s1;
                *reinterpret_cast<float2*>(o1 + j * 8) = v1;
            }
        }
    }
}

// ---------------- launch -----------------------------------------------------
extern "C" void kernel_launch(void* const* d_in, const int* in_sizes, int n_in,
                              void* d_out, int out_size) {
    (void)in_sizes; (void)n_in; (void)out_size;
    const float* x  = reinterpret_cast<const float*>(d_in[0]);
    const float* w  = reinterpret_cast<const float*>(d_in[1]);
    const float* nw = reinterpret_cast<const float*>(d_in[2]);
    float* y = reinterpret_cast<float*>(d_out);

    static bool attr_set = false;
    if (!attr_set) {
        cudaFuncSetAttribute(k_gemm_big, cudaFuncAttributeMaxDynamicSharedMemorySize, SMEMH);
        cudaFuncSetAttribute(k_gemm_rem, cudaFuncAttributeMaxDynamicSharedMemorySize, SMEMK);
        attr_set = true;
    }

    k_pre<<<4352, 256>>>(reinterpret_cast<const float4*>(w), x, nw);  // x quant + |W| partials
    k_quant_w<<<16384, 256>>>(reinterpret_cast<const float4*>(w));    // alpha + W quant
    k_gemm_big<<<BIG_TILES, 256, SMEMH>>>(y);        // 444 tiles = 3 clean waves
    k_gemm_rem<<<136, 256, SMEMK>>>(y);              // 68 tiles as 136 split-K halves
}

// round 16
// speedup vs baseline: 1.0508x; 1.0339x over previous
#include <cuda_runtime.h>
#include <cuda_bf16.h>
#include <cstdint>

#define DINLINE __device__ __forceinline__

// ---------------- scratch (device globals; no runtime allocation) ----------
__device__ float g_partial[256];
__device__ float g_scales[4096];                          // gamma/127 per token
__device__ float g_alpha_out;
__device__ __align__(128) __nv_bfloat16 g_wqh[16777216];  // W ternary bf16 [N,K]
__device__ __align__(128) __nv_bfloat16 g_xqh[16777216];  // x quant  bf16 [M,K]

// ---------------- PTX helpers (baseline ISA only) ---------------------------
DINLINE uint32_t smem_u32(const void* p) {
    uint32_t a;
    asm("{ .reg .u64 t; cvta.to.shared.u64 t, %1; cvt.u32.u64 %0, t; }"
        : "=r"(a) : "l"(p));
    return a;
}
DINLINE void cp16(uint32_t dst, const void* src) {
    asm volatile("cp.async.cg.shared.global [%0], [%1], 16;" :: "r"(dst), "l"(src));
}
DINLINE void cp_commit() { asm volatile("cp.async.commit_group;" ::: "memory"); }
DINLINE void cp_wait1()  { asm volatile("cp.async.wait_group 1;" ::: "memory"); }

DINLINE void ldsm_x4(uint32_t& r0, uint32_t& r1, uint32_t& r2, uint32_t& r3, uint32_t addr) {
    asm volatile("ldmatrix.sync.aligned.m8n8.x4.shared.b16 {%0,%1,%2,%3}, [%4];"
                 : "=r"(r0), "=r"(r1), "=r"(r2), "=r"(r3) : "r"(addr));
}
DINLINE void mma_bf16(float* c, uint32_t a0, uint32_t a1, uint32_t a2, uint32_t a3,
                      uint32_t b0, uint32_t b1) {
    asm volatile(
        "mma.sync.aligned.m16n8k16.row.col.f32.bf16.bf16.f32 "
        "{%0,%1,%2,%3}, {%4,%5,%6,%7}, {%8,%9}, {%0,%1,%2,%3};"
        : "+f"(c[0]), "+f"(c[1]), "+f"(c[2]), "+f"(c[3])
        : "r"(a0), "r"(a1), "r"(a2), "r"(a3), "r"(b0), "r"(b1));
}
DINLINE int clampi(int v, int lo, int hi) { return v < lo ? lo : (v > hi ? hi : v); }
DINLINE uint32_t pack_bf16(float a, float b) {
    __nv_bfloat162 h;
    h.x = __float2bfloat16(a);
    h.y = __float2bfloat16(b);
    return *reinterpret_cast<uint32_t*>(&h);
}

// ---------------- kernel 1: x RMSNorm+quant  MERGED WITH  |W| partial sums ---
// Blocks [0,4096): RMSNorm + int8-grid quantize one x row -> bf16 (g_scales=gamma/127).
// Blocks [4096,4352): |W| partial sums into g_partial (independent of x path).
__global__ void __launch_bounds__(256) k_pre(const float4* __restrict__ w,
                                             const float* __restrict__ x,
                                             const float* __restrict__ nw) {
    __shared__ float red[256];
    const int t = threadIdx.x;

    if (blockIdx.x >= 4096) {
        // ---- |W| partial sums ----
        const int b = blockIdx.x - 4096;
        const float4* p = w + (size_t)b * 16384;
        float s = 0.f;
#pragma unroll 8
        for (int i = 0; i < 64; i++) {
            float4 v = p[t + 256 * i];
            s += fabsf(v.x) + fabsf(v.y) + fabsf(v.z) + fabsf(v.w);
        }
        red[t] = s; __syncthreads();
#pragma unroll
        for (int o = 128; o > 0; o >>= 1) { if (t < o) red[t] += red[t + o]; __syncthreads(); }
        if (t == 0) g_partial[b] = red[0];
        return;
    }

    // ---- x path ----
    const int m = blockIdx.x;
    const float4* xr = reinterpret_cast<const float4*>(x + (size_t)m * 4096);
    const float4* nwr = reinterpret_cast<const float4*>(nw);

    float4 v[4], g[4];
    float ss = 0.f;
#pragma unroll
    for (int i = 0; i < 4; i++) {
        v[i] = xr[t + 256 * i];
        g[i] = nwr[t + 256 * i];
        ss += v[i].x * v[i].x + v[i].y * v[i].y + v[i].z * v[i].z + v[i].w * v[i].w;
    }
    red[t] = ss; __syncthreads();
#pragma unroll
    for (int o = 128; o > 0; o >>= 1) { if (t < o) red[t] += red[t + o]; __syncthreads(); }
    const float rinv = 1.0f / sqrtf(red[0] * (1.0f / 4096.0f) + 1e-6f);
    __syncthreads();

    float mx = 0.f;
#pragma unroll
    for (int i = 0; i < 4; i++) {
        v[i].x *= rinv * g[i].x; v[i].y *= rinv * g[i].y;
        v[i].z *= rinv * g[i].z; v[i].w *= rinv * g[i].w;
        mx = fmaxf(mx, fmaxf(fmaxf(fabsf(v[i].x), fabsf(v[i].y)),
                             fmaxf(fabsf(v[i].z), fabsf(v[i].w))));
    }
    red[t] = mx; __syncthreads();
#pragma unroll
    for (int o = 128; o > 0; o >>= 1) { if (t < o) red[t] = fmaxf(red[t], red[t + o]); __syncthreads(); }
    const float gamma = fmaxf(red[0], 1e-10f);
    if (t == 0) g_scales[m] = gamma * (1.0f / 127.0f);   // alpha applied in epilogue
    const float qs = 127.0f / gamma;
    uint2* dsth = reinterpret_cast<uint2*>(g_xqh) + (size_t)m * 1024;
#pragma unroll
    for (int i = 0; i < 4; i++) {
        int q0 = clampi(__float2int_rn(v[i].x * qs), -128, 127);
        int q1 = clampi(__float2int_rn(v[i].y * qs), -128, 127);
        int q2 = clampi(__float2int_rn(v[i].z * qs), -128, 127);
        int q3 = clampi(__float2int_rn(v[i].w * qs), -128, 127);
        uint2 h;
        h.x = pack_bf16((float)q0, (float)q1);
        h.y = pack_bf16((float)q2, (float)q3);
        dsth[t + 256 * i] = h;
    }
}

// ---------------- kernel 2: finalize alpha + ternary quantize W -> bf16 -----
__global__ void __launch_bounds__(256) k_quant_w(const float4* __restrict__ w) {
    __shared__ float red[256];
    const int t = threadIdx.x;
    red[t] = g_partial[t]; __syncthreads();
#pragma unroll
    for (int o = 128; o > 0; o >>= 1) { if (t < o) red[t] += red[t + o]; __syncthreads(); }
    const float alpha = fmaxf(red[0] * (1.0f / 16777216.0f), 1e-10f);
    if (blockIdx.x == 0 && t == 0) g_alpha_out = alpha;
    const float inv_alpha = 1.0f / alpha;

    const int idx = blockIdx.x * 256 + t;          // float4 index, 4194304 total
    float4 v = w[idx];
    int q0 = clampi(__float2int_rn(v.x * inv_alpha), -1, 1);
    int q1 = clampi(__float2int_rn(v.y * inv_alpha), -1, 1);
    int q2 = clampi(__float2int_rn(v.z * inv_alpha), -1, 1);
    int q3 = clampi(__float2int_rn(v.w * inv_alpha), -1, 1);
    uint2 h;
    h.x = pack_bf16((float)q0, (float)q1);
    h.y = pack_bf16((float)q2, (float)q3);
    reinterpret_cast<uint2*>(g_wqh)[idx] = h;
}

// Tile numbering: big-tile id T in [0,512): n0 = (T & 15)*256, m0 = (T >> 4)*128.
// Big kernel: T in [0,444) = exactly 3 clean waves of 148.
// Rem kernel: T in [444,512) as 136 N-split 128x128 tiles (R12-proven body).
static constexpr int BIG_TILES = 444;

static constexpr int LDS_PADH = 144;

// ================= GEMM big: 128x256 tile, 8 warps of 64x64 (R12 body) ======
static constexpr int A_SZ   = 128 * LDS_PADH;        // 18432
static constexpr int B_SZ   = 256 * LDS_PADH;        // 36864
static constexpr int STAGEH = A_SZ + B_SZ;           // 55296
static constexpr int SMEMH  = 4 * STAGEH;            // 221184

__global__ void __launch_bounds__(256, 1) k_gemm_big(float* __restrict__ out) {
    extern __shared__ char smemraw[];
    const uint32_t sbase = smem_u32(smemraw);
    const int t = threadIdx.x;
    const int lane = t & 31, wid = t >> 5;
    const int warpM = wid >> 2;          // 0..1  -> 64-row M slab
    const int warpN = wid & 3;           // 0..3  -> 64-col N slab
    const int T = blockIdx.x;
    const int m0 = (T >> 4) * 128, n0 = (T & 15) * 256;

    const char* gA = reinterpret_cast<const char*>(g_xqh) + (size_t)m0 * 8192;
    const char* gB = reinterpret_cast<const char*>(g_wqh) + (size_t)n0 * 8192;

    const int lr = t >> 1;               // 0..127
    const int lc = (t & 1) * 64;         // 0 or 64
    const char* pA = gA + (size_t)lr * 8192 + lc;
    const char* pB = gB + (size_t)lr * 8192 + lc;
    const uint32_t offA  = (uint32_t)(lr * LDS_PADH + lc);
    const uint32_t offB1 = (uint32_t)(A_SZ + lr * LDS_PADH + lc);
    const uint32_t offB2 = offB1 + 128 * LDS_PADH;

    const int xrow = (lane & 7) + ((lane >> 3) & 1) * 8;
    const int xcol = (lane >> 4) * 16;
    const uint32_t baseA = (uint32_t)((warpM * 64 + xrow) * LDS_PADH + xcol);
    const uint32_t baseB = (uint32_t)(A_SZ + (warpN * 64 + xrow) * LDS_PADH + xcol);

    float acc[4][8][4];
#pragma unroll
    for (int i = 0; i < 4; i++)
#pragma unroll
        for (int j = 0; j < 8; j++)
#pragma unroll
            for (int q = 0; q < 4; q++) acc[i][j][q] = 0.f;

    auto load_stage = [&](int s, int c) {
        const uint32_t dst = sbase + s * STAGEH;
        const char* sA = pA + (size_t)c * 128;
        const char* sB = pB + (size_t)c * 128;
#pragma unroll
        for (int i = 0; i < 4; i++) cp16(dst + offA  + i * 16, sA + i * 16);
#pragma unroll
        for (int i = 0; i < 4; i++) cp16(dst + offB1 + i * 16, sB + i * 16);
#pragma unroll
        for (int i = 0; i < 4; i++) cp16(dst + offB2 + i * 16, sB + (size_t)128 * 8192 + i * 16);
    };

    uint32_t a[2][4][4];
    uint32_t b[2][8][2];

    auto load_frags = [&](int buf, uint32_t st, int kk) {
#pragma unroll
        for (int i = 0; i < 4; i++)
            ldsm_x4(a[buf][i][0], a[buf][i][1], a[buf][i][2], a[buf][i][3],
                    st + baseA + i * (16 * LDS_PADH) + kk * 32);
#pragma unroll
        for (int j2 = 0; j2 < 4; j2++) {
            uint32_t q0, q1, q2, q3;
            ldsm_x4(q0, q1, q2, q3,
                    st + baseB + j2 * (16 * LDS_PADH) + kk * 32);
            b[buf][2 * j2][0] = q0; b[buf][2 * j2 + 1][0] = q1;
            b[buf][2 * j2][1] = q2; b[buf][2 * j2 + 1][1] = q3;
        }
    };

#pragma unroll
    for (int c = 0; c < 3; c++) { load_stage(c, c); cp_commit(); }
    cp_wait1();
    __syncthreads();
    load_frags(0, sbase, 0);

    for (int c = 0; c < 64; c++) {
        cp_wait1();
        __syncthreads();

        const int kn = c + 3;
        if (kn < 64) load_stage(kn & 3, kn);
        cp_commit();

        const uint32_t stC  = sbase + (c & 3) * STAGEH;
        const uint32_t stC1 = sbase + ((c + 1) & 3) * STAGEH;

#pragma unroll
        for (int kk = 0; kk < 4; kk++) {
            const int cur = kk & 1;
            const int nxt = cur ^ 1;
            if (kk < 3)        load_frags(nxt, stC, kk + 1);
            else if (c < 63)   load_frags(nxt, stC1, 0);
#pragma unroll
            for (int i = 0; i < 4; i++)
#pragma unroll
                for (int j = 0; j < 8; j++)
                    mma_bf16(acc[i][j], a[cur][i][0], a[cur][i][1],
                             a[cur][i][2], a[cur][i][3],
                             b[cur][j][0], b[cur][j][1]);
        }
    }

    const float alpha = g_alpha_out;
    const int rq = lane >> 2;
    const int cq = (lane & 3) * 2;
    const int nwcol = n0 + warpN * 64 + cq;
#pragma unroll
    for (int i = 0; i < 4; i++) {
        const int row = m0 + warpM * 64 + i * 16 + rq;
        const float s0 = g_scales[row] * alpha;
        const float s1 = g_scales[row + 8] * alpha;
        float* o0 = out + (size_t)row * 4096 + nwcol;
        float* o1 = o0 + (size_t)8 * 4096;
#pragma unroll
        for (int j = 0; j < 8; j++) {
            float2 v0; v0.x = acc[i][j][0] * s0; v0.y = acc[i][j][1] * s0;
            *reinterpret_cast<float2*>(o0 + j * 8) = v0;
            float2 v1; v1.x = acc[i][j][2] * s1; v1.y = acc[i][j][3] * s1;
            *reinterpret_cast<float2*>(o1 + j * 8) = v1;
        }
    }
}

// ================= GEMM rem: 128x128 tile, 8 warps of 64x32 (R12 body) ======
// Measured 85 us for the 136-tile wave in R12 — best of four tested variants.
static constexpr int A9_SZ   = 128 * LDS_PADH;       // 18432
static constexpr int STAGE9  = 2 * A9_SZ;            // 36864
static constexpr int SMEM9   = 4 * STAGE9;           // 147456

__global__ void __launch_bounds__(256, 1) k_gemm_rem(float* __restrict__ out) {
    extern __shared__ char smemraw[];
    const uint32_t sbase = smem_u32(smemraw);
    const int t = threadIdx.x;
    const int lane = t & 31, wid = t >> 5;
    const int warpM = wid >> 2, warpN = wid & 3;
    const int S = blockIdx.x;                        // 0..135
    const int T = BIG_TILES + (S >> 1);
    const int m0 = (T >> 4) * 128;
    const int n0 = (T & 15) * 256 + (S & 1) * 128;

    const char* gA = reinterpret_cast<const char*>(g_xqh) + (size_t)m0 * 8192;
    const char* gB = reinterpret_cast<const char*>(g_wqh) + (size_t)n0 * 8192;

    const int lr = t >> 1;
    const int lc = (t & 1) * 64;
    const char* pA = gA + (size_t)lr * 8192 + lc;
    const char* pB = gB + (size_t)lr * 8192 + lc;
    const uint32_t offA = (uint32_t)(lr * LDS_PADH + lc);
    const uint32_t offB = offA + A9_SZ;

    const int xrow = (lane & 7) + ((lane >> 3) & 1) * 8;
    const int xcol = (lane >> 4) * 16;
    const uint32_t baseA = (uint32_t)((warpM * 64 + xrow) * LDS_PADH + xcol);
    const uint32_t baseB = (uint32_t)(A9_SZ + (warpN * 32 + xrow) * LDS_PADH + xcol);

    float acc[4][4][4];
#pragma unroll
    for (int i = 0; i < 4; i++)
#pragma unroll
        for (int j = 0; j < 4; j++)
#pragma unroll
            for (int q = 0; q < 4; q++) acc[i][j][q] = 0.f;

    auto load_stage = [&](int s, int c) {
        const uint32_t dst = sbase + s * STAGE9;
        const char* sA = pA + (size_t)c * 128;
        const char* sB = pB + (size_t)c * 128;
#pragma unroll
        for (int i = 0; i < 4; i++) {
            cp16(dst + offA + i * 16, sA + i * 16);
            cp16(dst + offB + i * 16, sB + i * 16);
        }
    };

    uint32_t a[2][4][4];
    uint32_t b[2][4][2];

    auto load_frags = [&](int buf, uint32_t st, int kk) {
#pragma unroll
        for (int i = 0; i < 4; i++)
            ldsm_x4(a[buf][i][0], a[buf][i][1], a[buf][i][2], a[buf][i][3],
                    st + baseA + i * (16 * LDS_PADH) + kk * 32);
#pragma unroll
        for (int j2 = 0; j2 < 2; j2++) {
            uint32_t q0, q1, q2, q3;
            ldsm_x4(q0, q1, q2, q3,
                    st + baseB + j2 * (16 * LDS_PADH) + kk * 32);
            b[buf][2 * j2][0] = q0; b[buf][2 * j2 + 1][0] = q1;
            b[buf][2 * j2][1] = q2; b[buf][2 * j2 + 1][1] = q3;
        }
    };

#pragma unroll
    for (int c = 0; c < 3; c++) { load_stage(c, c); cp_commit(); }
    cp_wait1();
    __syncthreads();
    load_frags(0, sbase, 0);

    for (int c = 0; c < 64; c++) {
        cp_wait1();
        __syncthreads();

        const int kn = c + 3;
        if (kn < 64) load_stage(kn & 3, kn);
        cp_commit();

        const uint32_t stC  = sbase + (c & 3) * STAGE9;
        const uint32_t stC1 = sbase + ((c + 1) & 3) * STAGE9;

#pragma unroll
        for (int kk = 0; kk < 4; kk++) {
            const int cur = kk & 1;
            const int nxt = cur ^ 1;
            if (kk < 3)        load_frags(nxt, stC, kk + 1);
            else if (c < 63)   load_frags(nxt, stC1, 0);
#pragma unroll
            for (int i = 0; i < 4; i++)
#pragma unroll
                for (int j = 0; j < 4; j++)
                    mma_bf16(acc[i][j], a[cur][i][0], a[cur][i][1],
                             a[cur][i][2], a[cur][i][3],
                             b[cur][j][0], b[cur][j][1]);
        }
    }

    const float alpha = g_alpha_out;
    const int rq = lane >> 2;
    const int cq = (lane & 3) * 2;
    const int nwcol = n0 + warpN * 32 + cq;
#pragma unroll
    for (int i = 0; i < 4; i++) {
        const int row = m0 + warpM * 64 + i * 16 + rq;
        const float s0 = g_scales[row] * alpha;
        const float s1 = g_scales[row + 8] * alpha;
        float* o0 = out + (size_t)row * 4096 + nwcol;
        float* o1 = o0 + (size_t)8 * 4096;
#pragma unroll
        for (int j = 0; j < 4; j++) {
            float2 v0; v0.x = acc[i][j][0] * s0; v0.y = acc[i][j][1] * s0;
            *reinterpret_cast<float2*>(o0 + j * 8) = v0;
            float2 v1; v1.x = acc[i][j][2] * s1; v1.y = acc[i][j][3] * s1;
            *reinterpret_cast<float2*>(o1 + j * 8) = v1;
        }
    }
}

// ---------------- launch -----------------------------------------------------
extern "C" void kernel_launch(void* const* d_in, const int* in_sizes, int n_in,
                              void* d_out, int out_size) {
    (void)in_sizes; (void)n_in; (void)out_size;
    const float* x  = reinterpret_cast<const float*>(d_in[0]);
    const float* w  = reinterpret_cast<const float*>(d_in[1]);
    const float* nw = reinterpret_cast<const float*>(d_in[2]);
    float* y = reinterpret_cast<float*>(d_out);

    static bool attr_set = false;
    if (!attr_set) {
        cudaFuncSetAttribute(k_gemm_big, cudaFuncAttributeMaxDynamicSharedMemorySize, SMEMH);
        cudaFuncSetAttribute(k_gemm_rem, cudaFuncAttributeMaxDynamicSharedMemorySize, SMEM9);
        attr_set = true;
    }

    k_pre<<<4352, 256>>>(reinterpret_cast<const float4*>(w), x, nw);  // x quant + |W| partials
    k_quant_w<<<16384, 256>>>(reinterpret_cast<const float4*>(w));    // alpha + W quant
    k_gemm_big<<<BIG_TILES, 256, SMEMH>>>(y);        // 444 tiles = 3 clean waves
    k_gemm_rem<<<136, 256, SMEM9>>>(y);              // 68 tiles as 136 N-halves (R12 body)
}

// round 17
// speedup vs baseline: 1.0636x; 1.0122x over previous
#include <cuda_runtime.h>
#include <cuda_bf16.h>
#include <cstdint>

#define DINLINE __device__ __forceinline__

// ---------------- scratch (device globals; no runtime allocation) ----------
__device__ float g_partial[256];
__device__ float g_scales[4096];                          // gamma/127 per token
__device__ float g_alpha_out;
__device__ __align__(128) __nv_bfloat16 g_wqh[16777216];  // W ternary bf16 [N,K]
__device__ __align__(128) __nv_bfloat16 g_xqh[16777216];  // x quant  bf16 [M,K]

// ---------------- PTX helpers (baseline ISA only) ---------------------------
DINLINE uint32_t smem_u32(const void* p) {
    uint32_t a;
    asm("{ .reg .u64 t; cvta.to.shared.u64 t, %1; cvt.u32.u64 %0, t; }"
        : "=r"(a) : "l"(p));
    return a;
}
DINLINE void cp16(uint32_t dst, const void* src) {
    asm volatile("cp.async.cg.shared.global [%0], [%1], 16;" :: "r"(dst), "l"(src));
}
DINLINE void cp_commit() { asm volatile("cp.async.commit_group;" ::: "memory"); }
DINLINE void cp_wait1()  { asm volatile("cp.async.wait_group 1;" ::: "memory"); }

DINLINE void ldsm_x4(uint32_t& r0, uint32_t& r1, uint32_t& r2, uint32_t& r3, uint32_t addr) {
    asm volatile("ldmatrix.sync.aligned.m8n8.x4.shared.b16 {%0,%1,%2,%3}, [%4];"
                 : "=r"(r0), "=r"(r1), "=r"(r2), "=r"(r3) : "r"(addr));
}
DINLINE void mma_bf16(float* c, uint32_t a0, uint32_t a1, uint32_t a2, uint32_t a3,
                      uint32_t b0, uint32_t b1) {
    asm volatile(
        "mma.sync.aligned.m16n8k16.row.col.f32.bf16.bf16.f32 "
        "{%0,%1,%2,%3}, {%4,%5,%6,%7}, {%8,%9}, {%0,%1,%2,%3};"
        : "+f"(c[0]), "+f"(c[1]), "+f"(c[2]), "+f"(c[3])
        : "r"(a0), "r"(a1), "r"(a2), "r"(a3), "r"(b0), "r"(b1));
}
DINLINE int clampi(int v, int lo, int hi) { return v < lo ? lo : (v > hi ? hi : v); }
DINLINE uint32_t pack_bf16(float a, float b) {
    __nv_bfloat162 h;
    h.x = __float2bfloat16(a);
    h.y = __float2bfloat16(b);
    return *reinterpret_cast<uint32_t*>(&h);
}

// ---------------- kernel 1: x RMSNorm+quant  MERGED WITH  |W| partial sums ---
__global__ void __launch_bounds__(256) k_pre(const float4* __restrict__ w,
                                             const float* __restrict__ x,
                                             const float* __restrict__ nw) {
    __shared__ float red[256];
    const int t = threadIdx.x;

    if (blockIdx.x >= 4096) {
        // ---- |W| partial sums ----
        const int b = blockIdx.x - 4096;
        const float4* p = w + (size_t)b * 16384;
        float s = 0.f;
#pragma unroll 8
        for (int i = 0; i < 64; i++) {
            float4 v = p[t + 256 * i];
            s += fabsf(v.x) + fabsf(v.y) + fabsf(v.z) + fabsf(v.w);
        }
        red[t] = s; __syncthreads();
#pragma unroll
        for (int o = 128; o > 0; o >>= 1) { if (t < o) red[t] += red[t + o]; __syncthreads(); }
        if (t == 0) g_partial[b] = red[0];
        return;
    }

    // ---- x path ----
    const int m = blockIdx.x;
    const float4* xr = reinterpret_cast<const float4*>(x + (size_t)m * 4096);
    const float4* nwr = reinterpret_cast<const float4*>(nw);

    float4 v[4], g[4];
    float ss = 0.f;
#pragma unroll
    for (int i = 0; i < 4; i++) {
        v[i] = xr[t + 256 * i];
        g[i] = nwr[t + 256 * i];
        ss += v[i].x * v[i].x + v[i].y * v[i].y + v[i].z * v[i].z + v[i].w * v[i].w;
    }
    red[t] = ss; __syncthreads();
#pragma unroll
    for (int o = 128; o > 0; o >>= 1) { if (t < o) red[t] += red[t + o]; __syncthreads(); }
    const float rinv = 1.0f / sqrtf(red[0] * (1.0f / 4096.0f) + 1e-6f);
    __syncthreads();

    float mx = 0.f;
#pragma unroll
    for (int i = 0; i < 4; i++) {
        v[i].x *= rinv * g[i].x; v[i].y *= rinv * g[i].y;
        v[i].z *= rinv * g[i].z; v[i].w *= rinv * g[i].w;
        mx = fmaxf(mx, fmaxf(fmaxf(fabsf(v[i].x), fabsf(v[i].y)),
                             fmaxf(fabsf(v[i].z), fabsf(v[i].w))));
    }
    red[t] = mx; __syncthreads();
#pragma unroll
    for (int o = 128; o > 0; o >>= 1) { if (t < o) red[t] = fmaxf(red[t], red[t + o]); __syncthreads(); }
    const float gamma = fmaxf(red[0], 1e-10f);
    if (t == 0) g_scales[m] = gamma * (1.0f / 127.0f);   // alpha applied in epilogue
    const float qs = 127.0f / gamma;
    uint2* dsth = reinterpret_cast<uint2*>(g_xqh) + (size_t)m * 1024;
#pragma unroll
    for (int i = 0; i < 4; i++) {
        int q0 = clampi(__float2int_rn(v[i].x * qs), -128, 127);
        int q1 = clampi(__float2int_rn(v[i].y * qs), -128, 127);
        int q2 = clampi(__float2int_rn(v[i].z * qs), -128, 127);
        int q3 = clampi(__float2int_rn(v[i].w * qs), -128, 127);
        uint2 h;
        h.x = pack_bf16((float)q0, (float)q1);
        h.y = pack_bf16((float)q2, (float)q3);
        dsth[t + 256 * i] = h;
    }
}

// ---------------- kernel 2: finalize alpha (single block) --------------------
__global__ void __launch_bounds__(256) k_alpha() {
    __shared__ float red[256];
    const int t = threadIdx.x;
    red[t] = g_partial[t]; __syncthreads();
#pragma unroll
    for (int o = 128; o > 0; o >>= 1) { if (t < o) red[t] += red[t + o]; __syncthreads(); }
    if (t == 0) g_alpha_out = fmaxf(red[0] * (1.0f / 16777216.0f), 1e-10f);
}

// ---------------- kernel 3: ternary quantize W -> bf16 (pure stream) --------
__global__ void __launch_bounds__(256) k_quant_w(const float4* __restrict__ w) {
    const float inv_alpha = 1.0f / g_alpha_out;
    const int idx = blockIdx.x * 256 + threadIdx.x;    // float4 index, 4194304 total
    float4 v = w[idx];
    int q0 = clampi(__float2int_rn(v.x * inv_alpha), -1, 1);
    int q1 = clampi(__float2int_rn(v.y * inv_alpha), -1, 1);
    int q2 = clampi(__float2int_rn(v.z * inv_alpha), -1, 1);
    int q3 = clampi(__float2int_rn(v.w * inv_alpha), -1, 1);
    uint2 h;
    h.x = pack_bf16((float)q0, (float)q1);
    h.y = pack_bf16((float)q2, (float)q3);
    reinterpret_cast<uint2*>(g_wqh)[idx] = h;
}

// Tile numbering: big-tile id T in [0,512): n0 = (T & 15)*256, m0 = (T >> 4)*128.
// ONE merged GEMM kernel, grid = 580:
//   blocks [0,444):   big body, 128x256 tile, 8 warps of 64x64 (3 clean waves)
//   blocks [444,580): rem body, 128x128 tile, 8 warps of 64x32 (R12-proven),
//                     backfilling SMs as big's wave-3 stragglers drain.
static constexpr int BIG_TILES = 444;

static constexpr int LDS_PADH = 144;
static constexpr int A_SZ   = 128 * LDS_PADH;        // 18432
static constexpr int B_SZ   = 256 * LDS_PADH;        // 36864
static constexpr int STAGEH = A_SZ + B_SZ;           // 55296 (big stage)
static constexpr int SMEMH  = 4 * STAGEH;            // 221184
static constexpr int STAGE9 = 2 * A_SZ;              // 36864 (rem stage)

__global__ void __launch_bounds__(256, 1) k_gemm(float* __restrict__ out) {
    extern __shared__ char smemraw[];
    const uint32_t sbase = smem_u32(smemraw);
    const int t = threadIdx.x;
    const int lane = t & 31, wid = t >> 5;

    if (blockIdx.x < BIG_TILES) {
        // ================= BIG body (R16 k_gemm_big, verbatim) ==============
        const int warpM = wid >> 2;
        const int warpN = wid & 3;
        const int T = blockIdx.x;
        const int m0 = (T >> 4) * 128, n0 = (T & 15) * 256;

        const char* gA = reinterpret_cast<const char*>(g_xqh) + (size_t)m0 * 8192;
        const char* gB = reinterpret_cast<const char*>(g_wqh) + (size_t)n0 * 8192;

        const int lr = t >> 1;
        const int lc = (t & 1) * 64;
        const char* pA = gA + (size_t)lr * 8192 + lc;
        const char* pB = gB + (size_t)lr * 8192 + lc;
        const uint32_t offA  = (uint32_t)(lr * LDS_PADH + lc);
        const uint32_t offB1 = (uint32_t)(A_SZ + lr * LDS_PADH + lc);
        const uint32_t offB2 = offB1 + 128 * LDS_PADH;

        const int xrow = (lane & 7) + ((lane >> 3) & 1) * 8;
        const int xcol = (lane >> 4) * 16;
        const uint32_t baseA = (uint32_t)((warpM * 64 + xrow) * LDS_PADH + xcol);
        const uint32_t baseB = (uint32_t)(A_SZ + (warpN * 64 + xrow) * LDS_PADH + xcol);

        float acc[4][8][4];
#pragma unroll
        for (int i = 0; i < 4; i++)
#pragma unroll
            for (int j = 0; j < 8; j++)
#pragma unroll
                for (int q = 0; q < 4; q++) acc[i][j][q] = 0.f;

        auto load_stage = [&](int s, int c) {
            const uint32_t dst = sbase + s * STAGEH;
            const char* sA = pA + (size_t)c * 128;
            const char* sB = pB + (size_t)c * 128;
#pragma unroll
            for (int i = 0; i < 4; i++) cp16(dst + offA  + i * 16, sA + i * 16);
#pragma unroll
            for (int i = 0; i < 4; i++) cp16(dst + offB1 + i * 16, sB + i * 16);
#pragma unroll
            for (int i = 0; i < 4; i++) cp16(dst + offB2 + i * 16, sB + (size_t)128 * 8192 + i * 16);
        };

        uint32_t a[2][4][4];
        uint32_t b[2][8][2];

        auto load_frags = [&](int buf, uint32_t st, int kk) {
#pragma unroll
            for (int i = 0; i < 4; i++)
                ldsm_x4(a[buf][i][0], a[buf][i][1], a[buf][i][2], a[buf][i][3],
                        st + baseA + i * (16 * LDS_PADH) + kk * 32);
#pragma unroll
            for (int j2 = 0; j2 < 4; j2++) {
                uint32_t q0, q1, q2, q3;
                ldsm_x4(q0, q1, q2, q3,
                        st + baseB + j2 * (16 * LDS_PADH) + kk * 32);
                b[buf][2 * j2][0] = q0; b[buf][2 * j2 + 1][0] = q1;
                b[buf][2 * j2][1] = q2; b[buf][2 * j2 + 1][1] = q3;
            }
        };

#pragma unroll
        for (int c = 0; c < 3; c++) { load_stage(c, c); cp_commit(); }
        cp_wait1();
        __syncthreads();
        load_frags(0, sbase, 0);

        for (int c = 0; c < 64; c++) {
            cp_wait1();
            __syncthreads();

            const int kn = c + 3;
            if (kn < 64) load_stage(kn & 3, kn);
            cp_commit();

            const uint32_t stC  = sbase + (c & 3) * STAGEH;
            const uint32_t stC1 = sbase + ((c + 1) & 3) * STAGEH;

#pragma unroll
            for (int kk = 0; kk < 4; kk++) {
                const int cur = kk & 1;
                const int nxt = cur ^ 1;
                if (kk < 3)        load_frags(nxt, stC, kk + 1);
                else if (c < 63)   load_frags(nxt, stC1, 0);
#pragma unroll
                for (int i = 0; i < 4; i++)
#pragma unroll
                    for (int j = 0; j < 8; j++)
                        mma_bf16(acc[i][j], a[cur][i][0], a[cur][i][1],
                                 a[cur][i][2], a[cur][i][3],
                                 b[cur][j][0], b[cur][j][1]);
            }
        }

        const float alpha = g_alpha_out;
        const int rq = lane >> 2;
        const int cq = (lane & 3) * 2;
        const int nwcol = n0 + warpN * 64 + cq;
#pragma unroll
        for (int i = 0; i < 4; i++) {
            const int row = m0 + warpM * 64 + i * 16 + rq;
            const float s0 = g_scales[row] * alpha;
            const float s1 = g_scales[row + 8] * alpha;
            float* o0 = out + (size_t)row * 4096 + nwcol;
            float* o1 = o0 + (size_t)8 * 4096;
#pragma unroll
            for (int j = 0; j < 8; j++) {
                float2 v0; v0.x = acc[i][j][0] * s0; v0.y = acc[i][j][1] * s0;
                *reinterpret_cast<float2*>(o0 + j * 8) = v0;
                float2 v1; v1.x = acc[i][j][2] * s1; v1.y = acc[i][j][3] * s1;
                *reinterpret_cast<float2*>(o1 + j * 8) = v1;
            }
        }
    } else {
        // ================= REM body (R16 k_gemm_rem, verbatim) ==============
        const int warpM = wid >> 2, warpN = wid & 3;
        const int S = blockIdx.x - BIG_TILES;            // 0..135
        const int T = BIG_TILES + (S >> 1);
        const int m0 = (T >> 4) * 128;
        const int n0 = (T & 15) * 256 + (S & 1) * 128;

        const char* gA = reinterpret_cast<const char*>(g_xqh) + (size_t)m0 * 8192;
        const char* gB = reinterpret_cast<const char*>(g_wqh) + (size_t)n0 * 8192;

        const int lr = t >> 1;
        const int lc = (t & 1) * 64;
        const char* pA = gA + (size_t)lr * 8192 + lc;
        const char* pB = gB + (size_t)lr * 8192 + lc;
        const uint32_t offA = (uint32_t)(lr * LDS_PADH + lc);
        const uint32_t offB = offA + A_SZ;

        const int xrow = (lane & 7) + ((lane >> 3) & 1) * 8;
        const int xcol = (lane >> 4) * 16;
        const uint32_t baseA = (uint32_t)((warpM * 64 + xrow) * LDS_PADH + xcol);
        const uint32_t baseB = (uint32_t)(A_SZ + (warpN * 32 + xrow) * LDS_PADH + xcol);

        float acc[4][4][4];
#pragma unroll
        for (int i = 0; i < 4; i++)
#pragma unroll
            for (int j = 0; j < 4; j++)
#pragma unroll
                for (int q = 0; q < 4; q++) acc[i][j][q] = 0.f;

        auto load_stage = [&](int s, int c) {
            const uint32_t dst = sbase + s * STAGE9;
            const char* sA = pA + (size_t)c * 128;
            const char* sB = pB + (size_t)c * 128;
#pragma unroll
            for (int i = 0; i < 4; i++) {
                cp16(dst + offA + i * 16, sA + i * 16);
                cp16(dst + offB + i * 16, sB + i * 16);
            }
        };

        uint32_t a[2][4][4];
        uint32_t b[2][4][2];

        auto load_frags = [&](int buf, uint32_t st, int kk) {
#pragma unroll
            for (int i = 0; i < 4; i++)
                ldsm_x4(a[buf][i][0], a[buf][i][1], a[buf][i][2], a[buf][i][3],
                        st + baseA + i * (16 * LDS_PADH) + kk * 32);
#pragma unroll
            for (int j2 = 0; j2 < 2; j2++) {
                uint32_t q0, q1, q2, q3;
                ldsm_x4(q0, q1, q2, q3,
                        st + baseB + j2 * (16 * LDS_PADH) + kk * 32);
                b[buf][2 * j2][0] = q0; b[buf][2 * j2 + 1][0] = q1;
                b[buf][2 * j2][1] = q2; b[buf][2 * j2 + 1][1] = q3;
            }
        };

#pragma unroll
        for (int c = 0; c < 3; c++) { load_stage(c, c); cp_commit(); }
        cp_wait1();
        __syncthreads();
        load_frags(0, sbase, 0);

        for (int c = 0; c < 64; c++) {
            cp_wait1();
            __syncthreads();

            const int kn = c + 3;
            if (kn < 64) load_stage(kn & 3, kn);
            cp_commit();

            const uint32_t stC  = sbase + (c & 3) * STAGE9;
            const uint32_t stC1 = sbase + ((c + 1) & 3) * STAGE9;

#pragma unroll
            for (int kk = 0; kk < 4; kk++) {
                const int cur = kk & 1;
                const int nxt = cur ^ 1;
                if (kk < 3)        load_frags(nxt, stC, kk + 1);
                else if (c < 63)   load_frags(nxt, stC1, 0);
#pragma unroll
                for (int i = 0; i < 4; i++)
#pragma unroll
                    for (int j = 0; j < 4; j++)
                        mma_bf16(acc[i][j], a[cur][i][0], a[cur][i][1],
                                 a[cur][i][2], a[cur][i][3],
                                 b[cur][j][0], b[cur][j][1]);
            }
        }

        const float alpha = g_alpha_out;
        const int rq = lane >> 2;
        const int cq = (lane & 3) * 2;
        const int nwcol = n0 + warpN * 32 + cq;
#pragma unroll
        for (int i = 0; i < 4; i++) {
            const int row = m0 + warpM * 64 + i * 16 + rq;
            const float s0 = g_scales[row] * alpha;
            const float s1 = g_scales[row + 8] * alpha;
            float* o0 = out + (size_t)row * 4096 + nwcol;
            float* o1 = o0 + (size_t)8 * 4096;
#pragma unroll
            for (int j = 0; j < 4; j++) {
                float2 v0; v0.x = acc[i][j][0] * s0; v0.y = acc[i][j][1] * s0;
                *reinterpret_cast<float2*>(o0 + j * 8) = v0;
                float2 v1; v1.x = acc[i][j][2] * s1; v1.y = acc[i][j][3] * s1;
                *reinterpret_cast<float2*>(o1 + j * 8) = v1;
            }
        }
    }
}

// ---------------- launch -----------------------------------------------------
extern "C" void kernel_launch(void* const* d_in, const int* in_sizes, int n_in,
                              void* d_out, int out_size) {
    (void)in_sizes; (void)n_in; (void)out_size;
    const float* x  = reinterpret_cast<const float*>(d_in[0]);
    const float* w  = reinterpret_cast<const float*>(d_in[1]);
    const float* nw = reinterpret_cast<const float*>(d_in[2]);
    float* y = reinterpret_cast<float*>(d_out);

    static bool attr_set = false;
    if (!attr_set) {
        cudaFuncSetAttribute(k_gemm, cudaFuncAttributeMaxDynamicSharedMemorySize, SMEMH);
        attr_set = true;
    }

    k_pre<<<4352, 256>>>(reinterpret_cast<const float4*>(w), x, nw);  // x quant + |W| partials
    k_alpha<<<1, 256>>>();                                            // alpha (single block)
    k_quant_w<<<16384, 256>>>(reinterpret_cast<const float4*>(w));    // W quant (pure stream)
    k_gemm<<<BIG_TILES + 136, 256, SMEMH>>>(y);      // 444 big + 136 rem backfill
}